// round 8
// baseline (speedup 1.0000x reference)
#include <cuda_runtime.h>
#include <cstdint>

// Problem dims
#define B_  256
#define T_  64
#define K_  49
#define H_  512
#define A_  49
#define BT  (B_ * T_)            // 16384
#define BK  (B_ * K_)            // 12544
#define BTH ((size_t)BT * H_)    // 8388608
#define BTK ((size_t)BT * K_)    // 802816
#define CP  52                   // padded row pitch for scratch [*, 52]

// Scratch (device globals; no allocations allowed)
__device__ __align__(16) float g_cv[B_ * K_ * CP];   // content_v  [b,k,52]
__device__ __align__(16) float g_cg[B_ * T_ * CP];   // content_g  [b,t,52]
__device__ __align__(16) float g_cs[B_ * T_ * CP];   // s_t@Ws^T   [b,t,52]
__device__ __align__(16) float g_Wp[3 * 32768];      // permuted W fragments

typedef unsigned long long u64;

__device__ __forceinline__ float tanh_approx(float x) {
    float y;
    asm("tanh.approx.f32 %0, %1;" : "=f"(y) : "f"(x));
    return y;
}
__device__ __forceinline__ u64 pack2(float lo, float hi) {
    u64 d;
    asm("mov.b64 %0, {%1, %2};" : "=l"(d) : "f"(lo), "f"(hi));
    return d;
}
__device__ __forceinline__ uint32_t s2u(const void* p) {
    uint32_t a;
    asm("{ .reg .u64 t; cvta.to.shared.u64 t, %1; cvt.u32.u64 %0, t; }"
        : "=r"(a) : "l"(p));
    return a;
}
__device__ __forceinline__ void cpa16(uint32_t dst, const void* src) {
    asm volatile("cp.async.cg.shared.global [%0], [%1], 16;"
                 :: "r"(dst), "l"(src) : "memory");
}
__device__ __forceinline__ void prefetchL2(const void* p) {
    asm volatile("prefetch.global.L2 [%0];" :: "l"(p));
}
__device__ __forceinline__ float to_tf32(float x) {
    uint32_t y;
    asm("cvt.rna.tf32.f32 %0, %1;" : "=r"(y) : "f"(x));
    return __uint_as_float(y);
}
__device__ __forceinline__ void mma_tf32(float* d,
                                         float a0, float a1, float a2, float a3,
                                         float b0, float b1) {
    asm volatile(
        "mma.sync.aligned.m16n8k8.row.col.f32.tf32.tf32.f32 "
        "{%0,%1,%2,%3}, {%4,%5,%6,%7}, {%8,%9}, {%0,%1,%2,%3};"
        : "+f"(d[0]), "+f"(d[1]), "+f"(d[2]), "+f"(d[3])
        : "r"(__float_as_uint(a0)), "r"(__float_as_uint(a1)),
          "r"(__float_as_uint(a2)), "r"(__float_as_uint(a3)),
          "r"(__float_as_uint(b0)), "r"(__float_as_uint(b1)));
}

// ---------------------------------------------------------------------------
// Permute W matrices into mma.sync B-fragment order.
// ---------------------------------------------------------------------------
__global__ __launch_bounds__(128)
void wperm_kernel(const float* __restrict__ Wv, const float* __restrict__ Wg,
                  const float* __restrict__ Ws_)
{
    int tid = blockIdx.x * 128 + threadIdx.x;       // 0..24575
    int mat = tid / 8192;
    int rem = tid % 8192;
    int S   = rem / 128;
    int j   = (rem / 32) % 4;
    int l   = rem % 32;
    int g = l >> 2, tg = l & 3;
    int k = S * 8 + tg;
    int r0 = 16 * j + g, r1 = r0 + 8;
    const float* W = (mat == 0) ? Wv : (mat == 1) ? Wg : Ws_;
    float4 F;
    F.x = (r0 < A_) ? W[(size_t)r0 * H_ + k]     : 0.f;
    F.y = (r0 < A_) ? W[(size_t)r0 * H_ + k + 4] : 0.f;
    F.z = (r1 < A_) ? W[(size_t)r1 * H_ + k]     : 0.f;
    F.w = (r1 < A_) ? W[(size_t)r1 * H_ + k + 4] : 0.f;
    *(float4*)&g_Wp[(size_t)mat * 32768 + (size_t)rem * 4] = F;
}

// ---------------------------------------------------------------------------
// tf32 mma.sync content GEMM (unchanged).
// ---------------------------------------------------------------------------
__global__ __launch_bounds__(128, 3)
void gemm_mma_kernel(const float* __restrict__ V,   const float* __restrict__ h_t,
                     const float* __restrict__ s_t)
{
    __shared__ __align__(16) float  Xs[64][68];
    __shared__ __align__(16) float4 Bs[1024];       // [s][j][lane]

    const float* X; const float* wp; float* out; int row0;
    const int bid = blockIdx.x;
    if (bid < 196)      { X = V;   wp = g_Wp;          out = g_cv; row0 = bid * 64; }
    else if (bid < 452) { X = h_t; wp = g_Wp + 32768;  out = g_cg; row0 = (bid - 196) * 64; }
    else                { X = s_t; wp = g_Wp + 65536;  out = g_cs; row0 = (bid - 452) * 64; }

    const int tid  = threadIdx.x;
    const int wid  = tid >> 5;
    const int lane = tid & 31;
    const int g    = lane >> 2;
    const int tg   = lane & 3;
    const uint32_t xs_u = s2u(&Xs[0][0]);
    const uint32_t bs_u = s2u(&Bs[0]);

    float acc[8][4];
    #pragma unroll
    for (int n = 0; n < 8; n++)
        #pragma unroll
        for (int c = 0; c < 4; c++) acc[n][c] = 0.f;

    for (int c = 0; c < 8; c++) {
        __syncthreads();
        #pragma unroll
        for (int i = 0; i < 8; i++) {
            int idx = tid + i * 128;
            int r = idx >> 4, c4 = idx & 15;
            cpa16(xs_u + (uint32_t)(r * 68 + c4 * 4) * 4,
                  &X[(size_t)(row0 + r) * H_ + c * 64 + c4 * 4]);
        }
        #pragma unroll
        for (int i = 0; i < 8; i++) {
            int idx = tid + i * 128;
            cpa16(bs_u + (uint32_t)idx * 16, wp + (size_t)c * 4096 + (size_t)idx * 4);
        }
        asm volatile("cp.async.commit_group;" ::: "memory");
        asm volatile("cp.async.wait_group 0;" ::: "memory");
        __syncthreads();

        #pragma unroll
        for (int s = 0; s < 8; s++) {
            float a0 = Xs[16*wid + g    ][s*8 + tg    ];
            float a1 = Xs[16*wid + g + 8][s*8 + tg    ];
            float a2 = Xs[16*wid + g    ][s*8 + tg + 4];
            float a3 = Xs[16*wid + g + 8][s*8 + tg + 4];
            #pragma unroll
            for (int j = 0; j < 4; j++) {
                float4 bf = Bs[(s*4 + j) * 32 + lane];
                mma_tf32(acc[2*j],     a0, a1, a2, a3, bf.x, bf.y);
                mma_tf32(acc[2*j + 1], a0, a1, a2, a3, bf.z, bf.w);
            }
        }
    }

    const int r0g = row0 + 16 * wid + g;
    #pragma unroll
    for (int n = 0; n < 8; n++) {
        int col0 = n * 8 + tg * 2;
        if (col0 < CP) {
            *(u64*)&out[(size_t)r0g * CP + col0]       = pack2(acc[n][0], acc[n][1]);
            *(u64*)&out[(size_t)(r0g + 8) * CP + col0] = pack2(acc[n][2], acc[n][3]);
        }
    }
}

// ---------------------------------------------------------------------------
// zsoft: z_t + z_ext + softmax(alpha) + extended softmax(beta). (unchanged)
// ---------------------------------------------------------------------------
#define TZ 32
#define ZP 53

__global__ __launch_bounds__(256)
void zsoft_kernel(const float* __restrict__ Wh,
                  float* __restrict__ out_alpha, float* __restrict__ out_beta)
{
    const int b  = blockIdx.y;
    const int t0 = blockIdx.x * TZ;
    __shared__ float cvs[K_ * ZP];
    __shared__ float cgs[TZ * ZP];
    __shared__ float css[TZ * ZP];
    __shared__ float whs[A_];
    __shared__ float zes[TZ];
    __shared__ float zs[TZ * 50];
    const int tid = threadIdx.x;

    for (int i = tid; i < K_ * A_; i += 256) {
        int k = i / A_, a = i % A_;
        cvs[k * ZP + a] = g_cv[((size_t)b * K_ + k) * CP + a];
    }
    for (int i = tid; i < TZ * A_; i += 256) {
        int t = i / A_, a = i % A_;
        size_t src = ((size_t)b * T_ + t0 + t) * CP + a;
        cgs[t * ZP + a] = g_cg[src];
        css[t * ZP + a] = g_cs[src];
    }
    if (tid < A_) whs[tid] = Wh[tid];
    __syncthreads();

    for (int item = tid; item < TZ * K_ + TZ; item += 256) {
        const float* rowA;
        const float* rowB;
        if (item < TZ * K_) {
            int t = item / K_, k = item % K_;
            rowA = &cgs[t * ZP];
            rowB = &cvs[k * ZP];
        } else {
            int t = item - TZ * K_;
            rowA = &cgs[t * ZP];
            rowB = &css[t * ZP];
        }
        float s0 = 0.f, s1 = 0.f;
        #pragma unroll
        for (int a = 0; a < 48; a += 2) {
            s0 = fmaf(tanh_approx(rowA[a]   + rowB[a]),   whs[a],   s0);
            s1 = fmaf(tanh_approx(rowA[a+1] + rowB[a+1]), whs[a+1], s1);
        }
        s0 = fmaf(tanh_approx(rowA[48] + rowB[48]), whs[48], s0);
        float z = s0 + s1;
        if (item < TZ * K_) {
            int t = item / K_, k = item % K_;
            zs[t * 50 + k] = z;
        } else {
            zes[item - TZ * K_] = z;
        }
    }
    __syncthreads();

    const int warp = tid >> 5, lane = tid & 31;
    for (int t = warp; t < TZ; t += 8) {
        float z1 = (lane < K_)      ? zs[t*50 + lane]      : -1e30f;
        float z2 = (lane + 32 < K_) ? zs[t*50 + lane + 32] : -1e30f;
        float m = fmaxf(z1, z2);
        #pragma unroll
        for (int o = 16; o; o >>= 1) m = fmaxf(m, __shfl_xor_sync(0xffffffffu, m, o));
        float e1 = (lane < K_)      ? __expf(z1 - m) : 0.f;
        float e2 = (lane + 32 < K_) ? __expf(z2 - m) : 0.f;
        float s = e1 + e2;
        #pragma unroll
        for (int o = 16; o; o >>= 1) s += __shfl_xor_sync(0xffffffffu, s, o);
        float inv = 1.f / s;
        size_t bt = (size_t)b * T_ + t0 + t;
        if (lane < K_)      out_alpha[bt * K_ + lane]      = e1 * inv;
        if (lane + 32 < K_) out_alpha[bt * K_ + lane + 32] = e2 * inv;
        if (lane == 0) {
            float ze = zes[t];
            float m2 = fmaxf(m, ze);
            float ee = __expf(ze - m2);
            float denom = s * __expf(m - m2) + ee;
            out_beta[bt] = ee / denom;
        }
    }
}

// ---------------------------------------------------------------------------
// chat (per-batch pipelined, 3xTF32): c_hat = beta*s_t + (1-beta)*(alpha@V).
// Grid 256 (b), 256 thr. Double-buffered cp.async V chunks (4 x 49x128),
// alpha loaded once, s_t chunk c+1 L2-prefetched during compute of chunk c.
// 8 warps = 4 m16-tiles x 2 n64-halves per chunk. Dyn smem ~75.8KB -> 2 CTA/SM.
// ---------------------------------------------------------------------------
#define VP 136
#define AP 57
#define VFLTS (56 * VP)                                   // 7616 floats/buffer
#define SMEM_CHAT ((2 * VFLTS + T_ * AP + T_) * 4)        // 75776 bytes

__global__ __launch_bounds__(256)
void chat_mma_kernel(const float* __restrict__ V, const float* __restrict__ s_t,
                     const float* __restrict__ alpha, const float* __restrict__ beta,
                     float* __restrict__ out)
{
    extern __shared__ __align__(16) float dsm[];
    float* Vb[2] = { dsm, dsm + VFLTS };                  // [56][VP] each
    float (*as)[AP] = (float(*)[AP])(dsm + 2 * VFLTS);    // [64][57]
    float* bs = dsm + 2 * VFLTS + T_ * AP;

    const int b   = blockIdx.x;
    const int tid = threadIdx.x;
    const uint32_t vu[2] = { s2u(Vb[0]), s2u(Vb[1]) };

    // Zero pad rows 49..55 of both buffers (cp.async never touches them).
    for (int idx = tid; idx < 2 * 7 * 34; idx += 256) {
        int p = idx / 238, r = idx % 238;
        int k = 49 + r / 34, c = r % 34;
        *(float4*)&Vb[p][k * VP + c * 4] = make_float4(0.f, 0.f, 0.f, 0.f);
    }

    // Prefetch s_t chunk 0 into L2.
    {
        int t = tid >> 2, ln = tid & 3;
        prefetchL2(&s_t[((size_t)b * T_ + t) * H_ + ln * 32]);
    }

    // Issue V chunks 0 and 1.
    #pragma unroll
    for (int c0 = 0; c0 < 2; c0++) {
        for (int idx = tid; idx < K_ * 32; idx += 256) {
            int k = idx >> 5, cc = idx & 31;
            cpa16(vu[c0] + (uint32_t)(k * VP + cc * 4) * 4,
                  &V[((size_t)b * K_ + k) * H_ + c0 * 128 + cc * 4]);
        }
        asm volatile("cp.async.commit_group;" ::: "memory");
    }

    // alpha tile (cols >= 49 zero) + beta — overlaps with cp.async in flight.
    for (int i = tid; i < T_ * 56; i += 256) {
        int t = i / 56, k = i % 56;
        as[t][k] = (k < K_) ? alpha[((size_t)b * T_ + t) * K_ + k] : 0.f;
    }
    if (tid < T_) bs[tid] = beta[(size_t)b * T_ + tid];

    const int wid  = tid >> 5;
    const int lane = tid & 31;
    const int g    = lane >> 2;
    const int tg   = lane & 3;
    const int mw   = wid & 3;      // m16 tile (t-range 16mw..16mw+15)
    const int nh   = wid >> 2;     // n 64-half
    const int t0   = 16 * mw + g;

    for (int c = 0; c < 4; c++) {
        if (c < 3) asm volatile("cp.async.wait_group 1;" ::: "memory");
        else       asm volatile("cp.async.wait_group 0;" ::: "memory");
        __syncthreads();

        // Prefetch next s_t chunk while computing this one.
        if (c < 3) {
            int t = tid >> 2, ln = tid & 3;
            prefetchL2(&s_t[((size_t)b * T_ + t) * H_ + (c + 1) * 128 + ln * 32]);
        }

        const float* Vs = Vb[c & 1];
        float acc[8][4];
        #pragma unroll
        for (int j = 0; j < 8; j++)
            #pragma unroll
            for (int q = 0; q < 4; q++) acc[j][q] = 0.f;

        #pragma unroll
        for (int ks = 0; ks < 7; ks++) {
            float a0 = as[16*mw + g    ][ks*8 + tg    ];
            float a1 = as[16*mw + g + 8][ks*8 + tg    ];
            float a2 = as[16*mw + g    ][ks*8 + tg + 4];
            float a3 = as[16*mw + g + 8][ks*8 + tg + 4];
            float ah0 = to_tf32(a0), al0 = a0 - ah0;
            float ah1 = to_tf32(a1), al1 = a1 - ah1;
            float ah2 = to_tf32(a2), al2 = a2 - ah2;
            float ah3 = to_tf32(a3), al3 = a3 - ah3;
            #pragma unroll
            for (int j = 0; j < 8; j++) {
                int n = nh*64 + j*8 + g;
                float b0 = Vs[(ks*8 + tg    ) * VP + n];
                float b1 = Vs[(ks*8 + tg + 4) * VP + n];
                float bh0 = to_tf32(b0), bl0 = b0 - bh0;
                float bh1 = to_tf32(b1), bl1 = b1 - bh1;
                mma_tf32(acc[j], al0, al1, al2, al3, bh0, bh1);   // lo*hi
                mma_tf32(acc[j], ah0, ah1, ah2, ah3, bl0, bl1);   // hi*lo
                mma_tf32(acc[j], ah0, ah1, ah2, ah3, bh0, bh1);   // hi*hi
            }
        }

        __syncthreads();          // all warps done reading Vb[c&1]
        if (c + 2 < 4) {          // refill this buffer with chunk c+2
            for (int idx = tid; idx < K_ * 32; idx += 256) {
                int k = idx >> 5, cc = idx & 31;
                cpa16(vu[c & 1] + (uint32_t)(k * VP + cc * 4) * 4,
                      &V[((size_t)b * K_ + k) * H_ + (c + 2) * 128 + cc * 4]);
            }
            asm volatile("cp.async.commit_group;" ::: "memory");
        }

        // Blend epilogue (regs + gmem only) — overlaps the in-flight cp.async.
        const float bv0 = bs[t0],     ob0 = 1.f - bv0;
        const float bv1 = bs[t0 + 8], ob1 = 1.f - bv1;
        #pragma unroll
        for (int j = 0; j < 8; j++) {
            int col = c*128 + nh*64 + j*8 + 2*tg;
            size_t base0 = ((size_t)b * T_ + t0)     * H_ + col;
            size_t base1 = ((size_t)b * T_ + t0 + 8) * H_ + col;
            float2 s0 = *(const float2*)&s_t[base0];
            float2 s1 = *(const float2*)&s_t[base1];
            float2 o0, o1;
            o0.x = fmaf(bv0, s0.x, ob0 * acc[j][0]);
            o0.y = fmaf(bv0, s0.y, ob0 * acc[j][1]);
            o1.x = fmaf(bv1, s1.x, ob1 * acc[j][2]);
            o1.y = fmaf(bv1, s1.y, ob1 * acc[j][3]);
            *(float2*)&out[base0] = o0;
            *(float2*)&out[base1] = o1;
        }
    }
}

extern "C" void kernel_launch(void* const* d_in, const int* in_sizes, int n_in,
                              void* d_out, int out_size)
{
    (void)in_sizes; (void)n_in; (void)out_size;
    const float* V   = (const float*)d_in[0];   // (B,K,H)
    const float* h_t = (const float*)d_in[1];   // (B,T,H)
    const float* s_t = (const float*)d_in[2];   // (B,T,H)
    const float* Wv  = (const float*)d_in[3];   // (K,H)
    const float* Wg  = (const float*)d_in[4];   // (K,H)
    const float* Ws_ = (const float*)d_in[5];   // (K,H)
    const float* Wh  = (const float*)d_in[6];   // (1,K)

    float* out       = (float*)d_out;
    float* out_chat  = out;                 // (B,T,H)
    float* out_alpha = out + BTH;           // (B,T,K)
    float* out_beta  = out + BTH + BTK;     // (B,T,1)

    cudaFuncSetAttribute(chat_mma_kernel,
                         cudaFuncAttributeMaxDynamicSharedMemorySize, SMEM_CHAT);

    wperm_kernel<<<192, 128>>>(Wv, Wg, Ws_);
    gemm_mma_kernel<<<708, 128>>>(V, h_t, s_t);
    zsoft_kernel<<<dim3(2, B_), 256>>>(Wh, out_alpha, out_beta);
    chat_mma_kernel<<<B_, 256, SMEM_CHAT>>>(V, s_t, out_alpha, out_beta, out_chat);
}

// round 9
// speedup vs baseline: 1.1079x; 1.1079x over previous
#include <cuda_runtime.h>
#include <cstdint>

// Problem dims
#define B_  256
#define T_  64
#define K_  49
#define H_  512
#define A_  49
#define BT  (B_ * T_)            // 16384
#define BK  (B_ * K_)            // 12544
#define BTH ((size_t)BT * H_)    // 8388608
#define BTK ((size_t)BT * K_)    // 802816
#define CP  52                   // padded row pitch for scratch [*, 52]

// Scratch (device globals; no allocations allowed)
__device__ __align__(16) float g_cv[B_ * K_ * CP];   // content_v  [b,k,52]
__device__ __align__(16) float g_cg[B_ * T_ * CP];   // content_g  [b,t,52]
__device__ __align__(16) float g_cs[B_ * T_ * CP];   // s_t@Ws^T   [b,t,52]
__device__ __align__(16) float g_Wp[3 * 32768];      // permuted W fragments

typedef unsigned long long u64;

__device__ __forceinline__ float tanh_approx(float x) {
    float y;
    asm("tanh.approx.f32 %0, %1;" : "=f"(y) : "f"(x));
    return y;
}
__device__ __forceinline__ u64 pack2(float lo, float hi) {
    u64 d;
    asm("mov.b64 %0, {%1, %2};" : "=l"(d) : "f"(lo), "f"(hi));
    return d;
}
__device__ __forceinline__ uint32_t s2u(const void* p) {
    uint32_t a;
    asm("{ .reg .u64 t; cvta.to.shared.u64 t, %1; cvt.u32.u64 %0, t; }"
        : "=r"(a) : "l"(p));
    return a;
}
__device__ __forceinline__ void cpa16(uint32_t dst, const void* src) {
    asm volatile("cp.async.cg.shared.global [%0], [%1], 16;"
                 :: "r"(dst), "l"(src) : "memory");
}
__device__ __forceinline__ void prefetchL2(const void* p) {
    asm volatile("prefetch.global.L2 [%0];" :: "l"(p));
}
__device__ __forceinline__ void mma_tf32(float* d,
                                         float a0, float a1, float a2, float a3,
                                         float b0, float b1) {
    asm volatile(
        "mma.sync.aligned.m16n8k8.row.col.f32.tf32.tf32.f32 "
        "{%0,%1,%2,%3}, {%4,%5,%6,%7}, {%8,%9}, {%0,%1,%2,%3};"
        : "+f"(d[0]), "+f"(d[1]), "+f"(d[2]), "+f"(d[3])
        : "r"(__float_as_uint(a0)), "r"(__float_as_uint(a1)),
          "r"(__float_as_uint(a2)), "r"(__float_as_uint(a3)),
          "r"(__float_as_uint(b0)), "r"(__float_as_uint(b1)));
}
__device__ __forceinline__ void mma_bf16(float* d,
                                         uint32_t a0, uint32_t a1, uint32_t a2, uint32_t a3,
                                         uint32_t b0, uint32_t b1) {
    asm volatile(
        "mma.sync.aligned.m16n8k16.row.col.f32.bf16.bf16.f32 "
        "{%0,%1,%2,%3}, {%4,%5,%6,%7}, {%8,%9}, {%0,%1,%2,%3};"
        : "+f"(d[0]), "+f"(d[1]), "+f"(d[2]), "+f"(d[3])
        : "r"(a0), "r"(a1), "r"(a2), "r"(a3), "r"(b0), "r"(b1));
}
// pack {lo=x0, hi=x1} as bf16x2
__device__ __forceinline__ uint32_t bf2pack(float x0, float x1) {
    uint32_t h;
    asm("cvt.rn.bf16x2.f32 %0, %1, %2;" : "=r"(h) : "f"(x1), "f"(x0));
    return h;
}
// split (x0,x1) into hi bf16x2 and lo bf16x2
__device__ __forceinline__ void bf2split(float x0, float x1,
                                         uint32_t& hi, uint32_t& lo) {
    hi = bf2pack(x0, x1);
    float r0 = __uint_as_float(hi << 16);
    float r1 = __uint_as_float(hi & 0xffff0000u);
    lo = bf2pack(x0 - r0, x1 - r1);
}

// ---------------------------------------------------------------------------
// Permute W matrices into mma.sync B-fragment order.
// ---------------------------------------------------------------------------
__global__ __launch_bounds__(128)
void wperm_kernel(const float* __restrict__ Wv, const float* __restrict__ Wg,
                  const float* __restrict__ Ws_)
{
    int tid = blockIdx.x * 128 + threadIdx.x;       // 0..24575
    int mat = tid / 8192;
    int rem = tid % 8192;
    int S   = rem / 128;
    int j   = (rem / 32) % 4;
    int l   = rem % 32;
    int g = l >> 2, tg = l & 3;
    int k = S * 8 + tg;
    int r0 = 16 * j + g, r1 = r0 + 8;
    const float* W = (mat == 0) ? Wv : (mat == 1) ? Wg : Ws_;
    float4 F;
    F.x = (r0 < A_) ? W[(size_t)r0 * H_ + k]     : 0.f;
    F.y = (r0 < A_) ? W[(size_t)r0 * H_ + k + 4] : 0.f;
    F.z = (r1 < A_) ? W[(size_t)r1 * H_ + k]     : 0.f;
    F.w = (r1 < A_) ? W[(size_t)r1 * H_ + k + 4] : 0.f;
    *(float4*)&g_Wp[(size_t)mat * 32768 + (size_t)rem * 4] = F;
}

// ---------------------------------------------------------------------------
// tf32 mma.sync content GEMM (unchanged).
// ---------------------------------------------------------------------------
__global__ __launch_bounds__(128, 3)
void gemm_mma_kernel(const float* __restrict__ V,   const float* __restrict__ h_t,
                     const float* __restrict__ s_t)
{
    __shared__ __align__(16) float  Xs[64][68];
    __shared__ __align__(16) float4 Bs[1024];       // [s][j][lane]

    const float* X; const float* wp; float* out; int row0;
    const int bid = blockIdx.x;
    if (bid < 196)      { X = V;   wp = g_Wp;          out = g_cv; row0 = bid * 64; }
    else if (bid < 452) { X = h_t; wp = g_Wp + 32768;  out = g_cg; row0 = (bid - 196) * 64; }
    else                { X = s_t; wp = g_Wp + 65536;  out = g_cs; row0 = (bid - 452) * 64; }

    const int tid  = threadIdx.x;
    const int wid  = tid >> 5;
    const int lane = tid & 31;
    const int g    = lane >> 2;
    const int tg   = lane & 3;
    const uint32_t xs_u = s2u(&Xs[0][0]);
    const uint32_t bs_u = s2u(&Bs[0]);

    float acc[8][4];
    #pragma unroll
    for (int n = 0; n < 8; n++)
        #pragma unroll
        for (int c = 0; c < 4; c++) acc[n][c] = 0.f;

    for (int c = 0; c < 8; c++) {
        __syncthreads();
        #pragma unroll
        for (int i = 0; i < 8; i++) {
            int idx = tid + i * 128;
            int r = idx >> 4, c4 = idx & 15;
            cpa16(xs_u + (uint32_t)(r * 68 + c4 * 4) * 4,
                  &X[(size_t)(row0 + r) * H_ + c * 64 + c4 * 4]);
        }
        #pragma unroll
        for (int i = 0; i < 8; i++) {
            int idx = tid + i * 128;
            cpa16(bs_u + (uint32_t)idx * 16, wp + (size_t)c * 4096 + (size_t)idx * 4);
        }
        asm volatile("cp.async.commit_group;" ::: "memory");
        asm volatile("cp.async.wait_group 0;" ::: "memory");
        __syncthreads();

        #pragma unroll
        for (int s = 0; s < 8; s++) {
            float a0 = Xs[16*wid + g    ][s*8 + tg    ];
            float a1 = Xs[16*wid + g + 8][s*8 + tg    ];
            float a2 = Xs[16*wid + g    ][s*8 + tg + 4];
            float a3 = Xs[16*wid + g + 8][s*8 + tg + 4];
            #pragma unroll
            for (int j = 0; j < 4; j++) {
                float4 bf = Bs[(s*4 + j) * 32 + lane];
                mma_tf32(acc[2*j],     a0, a1, a2, a3, bf.x, bf.y);
                mma_tf32(acc[2*j + 1], a0, a1, a2, a3, bf.z, bf.w);
            }
        }
    }

    const int r0g = row0 + 16 * wid + g;
    #pragma unroll
    for (int n = 0; n < 8; n++) {
        int col0 = n * 8 + tg * 2;
        if (col0 < CP) {
            *(u64*)&out[(size_t)r0g * CP + col0]       = pack2(acc[n][0], acc[n][1]);
            *(u64*)&out[(size_t)(r0g + 8) * CP + col0] = pack2(acc[n][2], acc[n][3]);
        }
    }
}

// ---------------------------------------------------------------------------
// zsoft: z_t + z_ext + softmax(alpha) + extended softmax(beta). (unchanged)
// ---------------------------------------------------------------------------
#define TZ 32
#define ZP 53

__global__ __launch_bounds__(256)
void zsoft_kernel(const float* __restrict__ Wh,
                  float* __restrict__ out_alpha, float* __restrict__ out_beta)
{
    const int b  = blockIdx.y;
    const int t0 = blockIdx.x * TZ;
    __shared__ float cvs[K_ * ZP];
    __shared__ float cgs[TZ * ZP];
    __shared__ float css[TZ * ZP];
    __shared__ float whs[A_];
    __shared__ float zes[TZ];
    __shared__ float zs[TZ * 50];
    const int tid = threadIdx.x;

    for (int i = tid; i < K_ * A_; i += 256) {
        int k = i / A_, a = i % A_;
        cvs[k * ZP + a] = g_cv[((size_t)b * K_ + k) * CP + a];
    }
    for (int i = tid; i < TZ * A_; i += 256) {
        int t = i / A_, a = i % A_;
        size_t src = ((size_t)b * T_ + t0 + t) * CP + a;
        cgs[t * ZP + a] = g_cg[src];
        css[t * ZP + a] = g_cs[src];
    }
    if (tid < A_) whs[tid] = Wh[tid];
    __syncthreads();

    for (int item = tid; item < TZ * K_ + TZ; item += 256) {
        const float* rowA;
        const float* rowB;
        if (item < TZ * K_) {
            int t = item / K_, k = item % K_;
            rowA = &cgs[t * ZP];
            rowB = &cvs[k * ZP];
        } else {
            int t = item - TZ * K_;
            rowA = &cgs[t * ZP];
            rowB = &css[t * ZP];
        }
        float s0 = 0.f, s1 = 0.f;
        #pragma unroll
        for (int a = 0; a < 48; a += 2) {
            s0 = fmaf(tanh_approx(rowA[a]   + rowB[a]),   whs[a],   s0);
            s1 = fmaf(tanh_approx(rowA[a+1] + rowB[a+1]), whs[a+1], s1);
        }
        s0 = fmaf(tanh_approx(rowA[48] + rowB[48]), whs[48], s0);
        float z = s0 + s1;
        if (item < TZ * K_) {
            int t = item / K_, k = item % K_;
            zs[t * 50 + k] = z;
        } else {
            zes[item - TZ * K_] = z;
        }
    }
    __syncthreads();

    const int warp = tid >> 5, lane = tid & 31;
    for (int t = warp; t < TZ; t += 8) {
        float z1 = (lane < K_)      ? zs[t*50 + lane]      : -1e30f;
        float z2 = (lane + 32 < K_) ? zs[t*50 + lane + 32] : -1e30f;
        float m = fmaxf(z1, z2);
        #pragma unroll
        for (int o = 16; o; o >>= 1) m = fmaxf(m, __shfl_xor_sync(0xffffffffu, m, o));
        float e1 = (lane < K_)      ? __expf(z1 - m) : 0.f;
        float e2 = (lane + 32 < K_) ? __expf(z2 - m) : 0.f;
        float s = e1 + e2;
        #pragma unroll
        for (int o = 16; o; o >>= 1) s += __shfl_xor_sync(0xffffffffu, s, o);
        float inv = 1.f / s;
        size_t bt = (size_t)b * T_ + t0 + t;
        if (lane < K_)      out_alpha[bt * K_ + lane]      = e1 * inv;
        if (lane + 32 < K_) out_alpha[bt * K_ + lane + 32] = e2 * inv;
        if (lane == 0) {
            float ze = zes[t];
            float m2 = fmaxf(m, ze);
            float ee = __expf(ze - m2);
            float denom = s * __expf(m - m2) + ee;
            out_beta[bt] = ee / denom;
        }
    }
}

// ---------------------------------------------------------------------------
// chat via 2-term bf16-split m16n8k16 mma: c_hat = beta*s_t + (1-beta)*(alpha@V).
// Block (hc 128-wide, b); 256 thr = 8 warps = 4 m16-tiles x 2 n64-halves.
// V and alpha split ONCE at load into hi/lo bf16x2 smem tiles (k-pairs packed
// in u32). Inner loop: pure LDS + 3 HMMA.k16 per tile (hi*hi + hi*lo + lo*hi).
// Vhi/Vlo pitch 136 u32 and Ahi/Alo pitch 36 u32 -> conflict-free frag reads.
// ---------------------------------------------------------------------------
#define VPU 136            // u32 pitch of V hi/lo tiles [32 kpairs][128 n]
#define APU 36             // u32 pitch of A hi/lo tiles [64 t][32 kpairs]
#define V_U32 (32 * VPU)   // 4352
#define A_U32 (64 * APU)   // 2304
#define SMEM_CHAT ((2 * V_U32 + 2 * A_U32 + 64) * 4)   // 53504 bytes

__global__ __launch_bounds__(256)
void chat_mma_kernel(const float* __restrict__ V, const float* __restrict__ s_t,
                     const float* __restrict__ alpha, const float* __restrict__ beta,
                     float* __restrict__ out)
{
    extern __shared__ __align__(16) uint32_t csm[];
    uint32_t* Vhi = csm;
    uint32_t* Vlo = csm + V_U32;
    uint32_t* Ahi = csm + 2 * V_U32;
    uint32_t* Alo = csm + 2 * V_U32 + A_U32;
    float*    bsm = (float*)(csm + 2 * V_U32 + 2 * A_U32);

    const int b  = blockIdx.y;
    const int hc = blockIdx.x * 128;
    const int tid = threadIdx.x;

    // Prefetch the epilogue's s_t working set into L2.
    {
        int t = tid >> 2, ln = tid & 3;
        prefetchL2(&s_t[((size_t)b * T_ + t) * H_ + hc + ln * 32]);
    }

    // V tile: 25 kpairs x 32 float4-cols. kpair kp covers k = 2kp, 2kp+1.
    for (int idx = tid; idx < 25 * 32; idx += 256) {
        int kp = idx >> 5, n4 = idx & 31;
        const float* p0 = &V[((size_t)b * K_ + 2 * kp) * H_ + hc + n4 * 4];
        float4 x0 = *(const float4*)p0;
        float4 x1 = make_float4(0.f, 0.f, 0.f, 0.f);
        if (2 * kp + 1 < K_) x1 = *(const float4*)(p0 + H_);
        uint4 h, l;
        bf2split(x0.x, x1.x, h.x, l.x);
        bf2split(x0.y, x1.y, h.y, l.y);
        bf2split(x0.z, x1.z, h.z, l.z);
        bf2split(x0.w, x1.w, h.w, l.w);
        *(uint4*)&Vhi[kp * VPU + n4 * 4] = h;
        *(uint4*)&Vlo[kp * VPU + n4 * 4] = l;
    }
    // Zero pad kpairs 25..31 of V tiles.
    for (int idx = tid; idx < 2 * 7 * 32; idx += 256) {
        int p = idx / 224, r = idx % 224;
        int kp = 25 + r / 32, n4 = r % 32;
        uint32_t* dst = p ? Vlo : Vhi;
        *(uint4*)&dst[kp * VPU + n4 * 4] = make_uint4(0, 0, 0, 0);
    }
    // Alpha: 64 t x 32 kpairs (k >= 49 zero).
    for (int idx = tid; idx < 64 * 32; idx += 256) {
        int t = idx >> 5, kp = idx & 31;
        const float* ap = &alpha[((size_t)b * T_ + t) * K_];
        float x0 = (2 * kp     < K_) ? ap[2 * kp]     : 0.f;
        float x1 = (2 * kp + 1 < K_) ? ap[2 * kp + 1] : 0.f;
        uint32_t h, l;
        bf2split(x0, x1, h, l);
        Ahi[t * APU + kp] = h;
        Alo[t * APU + kp] = l;
    }
    if (tid < T_) bsm[tid] = beta[(size_t)b * T_ + tid];
    __syncthreads();

    const int wid  = tid >> 5;
    const int lane = tid & 31;
    const int g    = lane >> 2;
    const int tg   = lane & 3;
    const int mw   = wid & 3;      // m16 tile (t-range 16mw..16mw+15)
    const int nh   = wid >> 2;     // n 64-half
    const int row  = 16 * mw + g;

    float acc[8][4];
    #pragma unroll
    for (int j = 0; j < 8; j++)
        #pragma unroll
        for (int c = 0; c < 4; c++) acc[j][c] = 0.f;

    #pragma unroll
    for (int ks = 0; ks < 4; ks++) {
        uint32_t ah0 = Ahi[ row      * APU + ks*8 + tg    ];
        uint32_t ah1 = Ahi[(row + 8) * APU + ks*8 + tg    ];
        uint32_t ah2 = Ahi[ row      * APU + ks*8 + tg + 4];
        uint32_t ah3 = Ahi[(row + 8) * APU + ks*8 + tg + 4];
        uint32_t al0 = Alo[ row      * APU + ks*8 + tg    ];
        uint32_t al1 = Alo[(row + 8) * APU + ks*8 + tg    ];
        uint32_t al2 = Alo[ row      * APU + ks*8 + tg + 4];
        uint32_t al3 = Alo[(row + 8) * APU + ks*8 + tg + 4];
        #pragma unroll
        for (int j = 0; j < 8; j++) {
            int n = nh*64 + j*8 + g;
            uint32_t bh0 = Vhi[(ks*8 + tg    ) * VPU + n];
            uint32_t bh1 = Vhi[(ks*8 + tg + 4) * VPU + n];
            uint32_t bl0 = Vlo[(ks*8 + tg    ) * VPU + n];
            uint32_t bl1 = Vlo[(ks*8 + tg + 4) * VPU + n];
            mma_bf16(acc[j], ah0, ah1, ah2, ah3, bh0, bh1);   // hi*hi
            mma_bf16(acc[j], ah0, ah1, ah2, ah3, bl0, bl1);   // hi*lo
            mma_bf16(acc[j], al0, al1, al2, al3, bh0, bh1);   // lo*hi
        }
    }

    // Blend epilogue: D frag (g,2tg),(g,2tg+1),(g+8,2tg),(g+8,2tg+1)
    const float bv0 = bsm[row],     ob0 = 1.f - bv0;
    const float bv1 = bsm[row + 8], ob1 = 1.f - bv1;
    #pragma unroll
    for (int j = 0; j < 8; j++) {
        int col = hc + nh*64 + j*8 + 2*tg;
        size_t base0 = ((size_t)b * T_ + row)     * H_ + col;
        size_t base1 = ((size_t)b * T_ + row + 8) * H_ + col;
        float2 s0 = *(const float2*)&s_t[base0];
        float2 s1 = *(const float2*)&s_t[base1];
        float2 o0, o1;
        o0.x = fmaf(bv0, s0.x, ob0 * acc[j][0]);
        o0.y = fmaf(bv0, s0.y, ob0 * acc[j][1]);
        o1.x = fmaf(bv1, s1.x, ob1 * acc[j][2]);
        o1.y = fmaf(bv1, s1.y, ob1 * acc[j][3]);
        *(float2*)&out[base0] = o0;
        *(float2*)&out[base1] = o1;
    }
}

extern "C" void kernel_launch(void* const* d_in, const int* in_sizes, int n_in,
                              void* d_out, int out_size)
{
    (void)in_sizes; (void)n_in; (void)out_size;
    const float* V   = (const float*)d_in[0];   // (B,K,H)
    const float* h_t = (const float*)d_in[1];   // (B,T,H)
    const float* s_t = (const float*)d_in[2];   // (B,T,H)
    const float* Wv  = (const float*)d_in[3];   // (K,H)
    const float* Wg  = (const float*)d_in[4];   // (K,H)
    const float* Ws_ = (const float*)d_in[5];   // (K,H)
    const float* Wh  = (const float*)d_in[6];   // (1,K)

    float* out       = (float*)d_out;
    float* out_chat  = out;                 // (B,T,H)
    float* out_alpha = out + BTH;           // (B,T,K)
    float* out_beta  = out + BTH + BTK;     // (B,T,1)

    cudaFuncSetAttribute(chat_mma_kernel,
                         cudaFuncAttributeMaxDynamicSharedMemorySize, SMEM_CHAT);

    wperm_kernel<<<192, 128>>>(Wv, Wg, Ws_);
    gemm_mma_kernel<<<708, 128>>>(V, h_t, s_t);
    zsoft_kernel<<<dim3(2, B_), 256>>>(Wh, out_alpha, out_beta);
    chat_mma_kernel<<<dim3(4, B_), 256, SMEM_CHAT>>>(V, s_t, out_alpha, out_beta, out_chat);
}

// round 10
// speedup vs baseline: 1.2992x; 1.1727x over previous
#include <cuda_runtime.h>
#include <cstdint>

// Problem dims
#define B_  256
#define T_  64
#define K_  49
#define H_  512
#define A_  49
#define BT  (B_ * T_)            // 16384
#define BK  (B_ * K_)            // 12544
#define BTH ((size_t)BT * H_)    // 8388608
#define BTK ((size_t)BT * K_)    // 802816
#define CP  52                   // padded row pitch for scratch [*, 52]

// Scratch (device globals; no allocations allowed)
__device__ __align__(16) float g_cv[B_ * K_ * CP];   // content_v  [b,k,52]
__device__ __align__(16) float g_cg[B_ * T_ * CP];   // content_g  [b,t,52]
__device__ __align__(16) float g_cs[B_ * T_ * CP];   // s_t@Ws^T   [b,t,52]
__device__ __align__(16) float g_Wp[3 * 32768];      // permuted W fragments

typedef unsigned long long u64;

__device__ __forceinline__ float tanh_approx(float x) {
    float y;
    asm("tanh.approx.f32 %0, %1;" : "=f"(y) : "f"(x));
    return y;
}
__device__ __forceinline__ u64 pack2(float lo, float hi) {
    u64 d;
    asm("mov.b64 %0, {%1, %2};" : "=l"(d) : "f"(lo), "f"(hi));
    return d;
}
__device__ __forceinline__ uint32_t s2u(const void* p) {
    uint32_t a;
    asm("{ .reg .u64 t; cvta.to.shared.u64 t, %1; cvt.u32.u64 %0, t; }"
        : "=r"(a) : "l"(p));
    return a;
}
__device__ __forceinline__ void cpa16(uint32_t dst, const void* src) {
    asm volatile("cp.async.cg.shared.global [%0], [%1], 16;"
                 :: "r"(dst), "l"(src) : "memory");
}
__device__ __forceinline__ void prefetchL2(const void* p) {
    asm volatile("prefetch.global.L2 [%0];" :: "l"(p));
}
__device__ __forceinline__ void mma_tf32(float* d,
                                         float a0, float a1, float a2, float a3,
                                         float b0, float b1) {
    asm volatile(
        "mma.sync.aligned.m16n8k8.row.col.f32.tf32.tf32.f32 "
        "{%0,%1,%2,%3}, {%4,%5,%6,%7}, {%8,%9}, {%0,%1,%2,%3};"
        : "+f"(d[0]), "+f"(d[1]), "+f"(d[2]), "+f"(d[3])
        : "r"(__float_as_uint(a0)), "r"(__float_as_uint(a1)),
          "r"(__float_as_uint(a2)), "r"(__float_as_uint(a3)),
          "r"(__float_as_uint(b0)), "r"(__float_as_uint(b1)));
}
__device__ __forceinline__ void mma_bf16(float* d,
                                         uint32_t a0, uint32_t a1, uint32_t a2, uint32_t a3,
                                         uint32_t b0, uint32_t b1) {
    asm volatile(
        "mma.sync.aligned.m16n8k16.row.col.f32.bf16.bf16.f32 "
        "{%0,%1,%2,%3}, {%4,%5,%6,%7}, {%8,%9}, {%0,%1,%2,%3};"
        : "+f"(d[0]), "+f"(d[1]), "+f"(d[2]), "+f"(d[3])
        : "r"(a0), "r"(a1), "r"(a2), "r"(a3), "r"(b0), "r"(b1));
}
__device__ __forceinline__ uint32_t bf2pack(float x0, float x1) {
    uint32_t h;
    asm("cvt.rn.bf16x2.f32 %0, %1, %2;" : "=r"(h) : "f"(x1), "f"(x0));
    return h;
}
__device__ __forceinline__ void bf2split(float x0, float x1,
                                         uint32_t& hi, uint32_t& lo) {
    hi = bf2pack(x0, x1);
    float r0 = __uint_as_float(hi << 16);
    float r1 = __uint_as_float(hi & 0xffff0000u);
    lo = bf2pack(x0 - r0, x1 - r1);
}

// ---------------------------------------------------------------------------
// Permute W matrices into mma.sync B-fragment order.
// ---------------------------------------------------------------------------
__global__ __launch_bounds__(128)
void wperm_kernel(const float* __restrict__ Wv, const float* __restrict__ Wg,
                  const float* __restrict__ Ws_)
{
    int tid = blockIdx.x * 128 + threadIdx.x;       // 0..24575
    int mat = tid / 8192;
    int rem = tid % 8192;
    int S   = rem / 128;
    int j   = (rem / 32) % 4;
    int l   = rem % 32;
    int g = l >> 2, tg = l & 3;
    int k = S * 8 + tg;
    int r0 = 16 * j + g, r1 = r0 + 8;
    const float* W = (mat == 0) ? Wv : (mat == 1) ? Wg : Ws_;
    float4 F;
    F.x = (r0 < A_) ? W[(size_t)r0 * H_ + k]     : 0.f;
    F.y = (r0 < A_) ? W[(size_t)r0 * H_ + k + 4] : 0.f;
    F.z = (r1 < A_) ? W[(size_t)r1 * H_ + k]     : 0.f;
    F.w = (r1 < A_) ? W[(size_t)r1 * H_ + k + 4] : 0.f;
    *(float4*)&g_Wp[(size_t)mat * 32768 + (size_t)rem * 4] = F;
}

// ---------------------------------------------------------------------------
// tf32 mma.sync content GEMM, double-buffered K=32 chunks, 4 CTA/SM.
//   seg 0: 196 blocks  V -> g_cv ; seg 1: 256 h_t -> g_cg ; seg 2: 256 s_t -> g_cs
// CTA: 128 thr (4 warps), tile M=64 x N=64, K in 16 chunks of 32.
// Pipeline: issue chunk c+1's cp.async before waiting on chunk c.
// ---------------------------------------------------------------------------
#define XPW 36     // X smem pitch (floats)

__global__ __launch_bounds__(128, 4)
void gemm_mma_kernel(const float* __restrict__ V,   const float* __restrict__ h_t,
                     const float* __restrict__ s_t)
{
    __shared__ __align__(16) float Xs[2][64][XPW];
    __shared__ __align__(16) float Bs[2][2048];

    const float* X; const float* wp; float* out; int row0;
    const int bid = blockIdx.x;
    if (bid < 196)      { X = V;   wp = g_Wp;          out = g_cv; row0 = bid * 64; }
    else if (bid < 452) { X = h_t; wp = g_Wp + 32768;  out = g_cg; row0 = (bid - 196) * 64; }
    else                { X = s_t; wp = g_Wp + 65536;  out = g_cs; row0 = (bid - 452) * 64; }

    const int tid  = threadIdx.x;
    const int wid  = tid >> 5;
    const int lane = tid & 31;
    const int g    = lane >> 2;
    const int tg   = lane & 3;
    const uint32_t xs_u[2] = { s2u(&Xs[0][0][0]), s2u(&Xs[1][0][0]) };
    const uint32_t bs_u[2] = { s2u(&Bs[0][0]),    s2u(&Bs[1][0]) };

    // chunk loader: X 512 f4 (64 rows x 8), B 512 f4 linear
    auto load_chunk = [&](int c) {
        const int p = c & 1;
        #pragma unroll
        for (int i = 0; i < 4; i++) {
            int idx = tid + i * 128;
            int r = idx >> 3, c4 = idx & 7;
            cpa16(xs_u[p] + (uint32_t)(r * XPW + c4 * 4) * 4,
                  &X[(size_t)(row0 + r) * H_ + c * 32 + c4 * 4]);
        }
        #pragma unroll
        for (int i = 0; i < 4; i++) {
            int idx = tid + i * 128;
            cpa16(bs_u[p] + (uint32_t)idx * 16, wp + (size_t)c * 2048 + (size_t)idx * 4);
        }
        asm volatile("cp.async.commit_group;" ::: "memory");
    };

    float acc[8][4];
    #pragma unroll
    for (int n = 0; n < 8; n++)
        #pragma unroll
        for (int c = 0; c < 4; c++) acc[n][c] = 0.f;

    load_chunk(0);
    for (int c = 0; c < 16; c++) {
        if (c + 1 < 16) {
            load_chunk(c + 1);
            asm volatile("cp.async.wait_group 1;" ::: "memory");
        } else {
            asm volatile("cp.async.wait_group 0;" ::: "memory");
        }
        __syncthreads();

        const int p = c & 1;
        #pragma unroll
        for (int s = 0; s < 4; s++) {
            float a0 = Xs[p][16*wid + g    ][s*8 + tg    ];
            float a1 = Xs[p][16*wid + g + 8][s*8 + tg    ];
            float a2 = Xs[p][16*wid + g    ][s*8 + tg + 4];
            float a3 = Xs[p][16*wid + g + 8][s*8 + tg + 4];
            #pragma unroll
            for (int j = 0; j < 4; j++) {
                float4 bf = *(const float4*)&Bs[p][((s*4 + j) * 32 + lane) * 4];
                mma_tf32(acc[2*j],     a0, a1, a2, a3, bf.x, bf.y);
                mma_tf32(acc[2*j + 1], a0, a1, a2, a3, bf.z, bf.w);
            }
        }
        __syncthreads();   // all warps done with buf p before chunk c+2 refills it
    }

    const int r0g = row0 + 16 * wid + g;
    #pragma unroll
    for (int n = 0; n < 8; n++) {
        int col0 = n * 8 + tg * 2;
        if (col0 < CP) {
            *(u64*)&out[(size_t)r0g * CP + col0]       = pack2(acc[n][0], acc[n][1]);
            *(u64*)&out[(size_t)(r0g + 8) * CP + col0] = pack2(acc[n][2], acc[n][3]);
        }
    }
}

// ---------------------------------------------------------------------------
// zsoft: z_t + z_ext + softmax(alpha) + extended softmax(beta).
// Grid (4, B): block handles 16 t-rows. 256 threads. Vectorized f4 tanh loop.
// ---------------------------------------------------------------------------
#define TZ 16
#define ZP 52

__global__ __launch_bounds__(256)
void zsoft_kernel(const float* __restrict__ Wh,
                  float* __restrict__ out_alpha, float* __restrict__ out_beta)
{
    const int b  = blockIdx.y;
    const int t0 = blockIdx.x * TZ;
    __shared__ __align__(16) float cvs[K_ * ZP];
    __shared__ __align__(16) float cgs[TZ * ZP];
    __shared__ __align__(16) float css[TZ * ZP];
    __shared__ __align__(16) float whs[52];
    __shared__ float zes[TZ];
    __shared__ float zs[TZ * 50];
    const int tid = threadIdx.x;

    // f4 copies from gmem scratch (both pitch 52, 16B aligned)
    for (int i = tid; i < K_ * 13; i += 256) {
        int k = i / 13, c4 = i % 13;
        *(float4*)&cvs[k * ZP + c4*4] =
            *(const float4*)&g_cv[((size_t)b * K_ + k) * CP + c4*4];
    }
    for (int i = tid; i < TZ * 13; i += 256) {
        int t = i / 13, c4 = i % 13;
        size_t src = ((size_t)b * T_ + t0 + t) * CP + c4*4;
        *(float4*)&cgs[t * ZP + c4*4] = *(const float4*)&g_cg[src];
        *(float4*)&css[t * ZP + c4*4] = *(const float4*)&g_cs[src];
    }
    if (tid < 52) whs[tid] = (tid < A_) ? Wh[tid] : 0.f;
    __syncthreads();

    // items 0..TZ*K-1 : z_t ;  items TZ*K..TZ*K+TZ-1 : z_ext
    for (int item = tid; item < TZ * K_ + TZ; item += 256) {
        const float* rowA;
        const float* rowB;
        if (item < TZ * K_) {
            int t = item / K_, k = item % K_;
            rowA = &cgs[t * ZP];
            rowB = &cvs[k * ZP];
        } else {
            int t = item - TZ * K_;
            rowA = &cgs[t * ZP];
            rowB = &css[t * ZP];
        }
        float s0 = 0.f, s1 = 0.f, s2 = 0.f, s3 = 0.f;
        #pragma unroll
        for (int a = 0; a < 48; a += 4) {
            float4 A = *(const float4*)&rowA[a];
            float4 Bv = *(const float4*)&rowB[a];
            float4 W = *(const float4*)&whs[a];
            s0 = fmaf(tanh_approx(A.x + Bv.x), W.x, s0);
            s1 = fmaf(tanh_approx(A.y + Bv.y), W.y, s1);
            s2 = fmaf(tanh_approx(A.z + Bv.z), W.z, s2);
            s3 = fmaf(tanh_approx(A.w + Bv.w), W.w, s3);
        }
        s0 = fmaf(tanh_approx(rowA[48] + rowB[48]), whs[48], s0);
        float z = (s0 + s1) + (s2 + s3);
        if (item < TZ * K_) {
            int t = item / K_, k = item % K_;
            zs[t * 50 + k] = z;
        } else {
            zes[item - TZ * K_] = z;
        }
    }
    __syncthreads();

    const int warp = tid >> 5, lane = tid & 31;
    for (int t = warp; t < TZ; t += 8) {
        float z1 = (lane < K_)      ? zs[t*50 + lane]      : -1e30f;
        float z2 = (lane + 32 < K_) ? zs[t*50 + lane + 32] : -1e30f;
        float m = fmaxf(z1, z2);
        #pragma unroll
        for (int o = 16; o; o >>= 1) m = fmaxf(m, __shfl_xor_sync(0xffffffffu, m, o));
        float e1 = (lane < K_)      ? __expf(z1 - m) : 0.f;
        float e2 = (lane + 32 < K_) ? __expf(z2 - m) : 0.f;
        float s = e1 + e2;
        #pragma unroll
        for (int o = 16; o; o >>= 1) s += __shfl_xor_sync(0xffffffffu, s, o);
        float inv = 1.f / s;
        size_t bt = (size_t)b * T_ + t0 + t;
        if (lane < K_)      out_alpha[bt * K_ + lane]      = e1 * inv;
        if (lane + 32 < K_) out_alpha[bt * K_ + lane + 32] = e2 * inv;
        if (lane == 0) {
            float ze = zes[t];
            float m2 = fmaxf(m, ze);
            float ee = __expf(ze - m2);
            float denom = s * __expf(m - m2) + ee;
            out_beta[bt] = ee / denom;
        }
    }
}

// ---------------------------------------------------------------------------
// chat via 2-term bf16-split m16n8k16 mma (unchanged from round 9).
// ---------------------------------------------------------------------------
#define VPU 136            // u32 pitch of V hi/lo tiles [32 kpairs][128 n]
#define APU 36             // u32 pitch of A hi/lo tiles [64 t][32 kpairs]
#define V_U32 (32 * VPU)   // 4352
#define A_U32 (64 * APU)   // 2304
#define SMEM_CHAT ((2 * V_U32 + 2 * A_U32 + 64) * 4)   // 53504 bytes

__global__ __launch_bounds__(256)
void chat_mma_kernel(const float* __restrict__ V, const float* __restrict__ s_t,
                     const float* __restrict__ alpha, const float* __restrict__ beta,
                     float* __restrict__ out)
{
    extern __shared__ __align__(16) uint32_t csm[];
    uint32_t* Vhi = csm;
    uint32_t* Vlo = csm + V_U32;
    uint32_t* Ahi = csm + 2 * V_U32;
    uint32_t* Alo = csm + 2 * V_U32 + A_U32;
    float*    bsm = (float*)(csm + 2 * V_U32 + 2 * A_U32);

    const int b  = blockIdx.y;
    const int hc = blockIdx.x * 128;
    const int tid = threadIdx.x;

    {
        int t = tid >> 2, ln = tid & 3;
        prefetchL2(&s_t[((size_t)b * T_ + t) * H_ + hc + ln * 32]);
    }

    for (int idx = tid; idx < 25 * 32; idx += 256) {
        int kp = idx >> 5, n4 = idx & 31;
        const float* p0 = &V[((size_t)b * K_ + 2 * kp) * H_ + hc + n4 * 4];
        float4 x0 = *(const float4*)p0;
        float4 x1 = make_float4(0.f, 0.f, 0.f, 0.f);
        if (2 * kp + 1 < K_) x1 = *(const float4*)(p0 + H_);
        uint4 h, l;
        bf2split(x0.x, x1.x, h.x, l.x);
        bf2split(x0.y, x1.y, h.y, l.y);
        bf2split(x0.z, x1.z, h.z, l.z);
        bf2split(x0.w, x1.w, h.w, l.w);
        *(uint4*)&Vhi[kp * VPU + n4 * 4] = h;
        *(uint4*)&Vlo[kp * VPU + n4 * 4] = l;
    }
    for (int idx = tid; idx < 2 * 7 * 32; idx += 256) {
        int p = idx / 224, r = idx % 224;
        int kp = 25 + r / 32, n4 = r % 32;
        uint32_t* dst = p ? Vlo : Vhi;
        *(uint4*)&dst[kp * VPU + n4 * 4] = make_uint4(0, 0, 0, 0);
    }
    for (int idx = tid; idx < 64 * 32; idx += 256) {
        int t = idx >> 5, kp = idx & 31;
        const float* ap = &alpha[((size_t)b * T_ + t) * K_];
        float x0 = (2 * kp     < K_) ? ap[2 * kp]     : 0.f;
        float x1 = (2 * kp + 1 < K_) ? ap[2 * kp + 1] : 0.f;
        uint32_t h, l;
        bf2split(x0, x1, h, l);
        Ahi[t * APU + kp] = h;
        Alo[t * APU + kp] = l;
    }
    if (tid < T_) bsm[tid] = beta[(size_t)b * T_ + tid];
    __syncthreads();

    const int wid  = tid >> 5;
    const int lane = tid & 31;
    const int g    = lane >> 2;
    const int tg   = lane & 3;
    const int mw   = wid & 3;
    const int nh   = wid >> 2;
    const int row  = 16 * mw + g;

    float acc[8][4];
    #pragma unroll
    for (int j = 0; j < 8; j++)
        #pragma unroll
        for (int c = 0; c < 4; c++) acc[j][c] = 0.f;

    #pragma unroll
    for (int ks = 0; ks < 4; ks++) {
        uint32_t ah0 = Ahi[ row      * APU + ks*8 + tg    ];
        uint32_t ah1 = Ahi[(row + 8) * APU + ks*8 + tg    ];
        uint32_t ah2 = Ahi[ row      * APU + ks*8 + tg + 4];
        uint32_t ah3 = Ahi[(row + 8) * APU + ks*8 + tg + 4];
        uint32_t al0 = Alo[ row      * APU + ks*8 + tg    ];
        uint32_t al1 = Alo[(row + 8) * APU + ks*8 + tg    ];
        uint32_t al2 = Alo[ row      * APU + ks*8 + tg + 4];
        uint32_t al3 = Alo[(row + 8) * APU + ks*8 + tg + 4];
        #pragma unroll
        for (int j = 0; j < 8; j++) {
            int n = nh*64 + j*8 + g;
            uint32_t bh0 = Vhi[(ks*8 + tg    ) * VPU + n];
            uint32_t bh1 = Vhi[(ks*8 + tg + 4) * VPU + n];
            uint32_t bl0 = Vlo[(ks*8 + tg    ) * VPU + n];
            uint32_t bl1 = Vlo[(ks*8 + tg + 4) * VPU + n];
            mma_bf16(acc[j], ah0, ah1, ah2, ah3, bh0, bh1);   // hi*hi
            mma_bf16(acc[j], ah0, ah1, ah2, ah3, bl0, bl1);   // hi*lo
            mma_bf16(acc[j], al0, al1, al2, al3, bh0, bh1);   // lo*hi
        }
    }

    const float bv0 = bsm[row],     ob0 = 1.f - bv0;
    const float bv1 = bsm[row + 8], ob1 = 1.f - bv1;
    #pragma unroll
    for (int j = 0; j < 8; j++) {
        int col = hc + nh*64 + j*8 + 2*tg;
        size_t base0 = ((size_t)b * T_ + row)     * H_ + col;
        size_t base1 = ((size_t)b * T_ + row + 8) * H_ + col;
        float2 s0 = *(const float2*)&s_t[base0];
        float2 s1 = *(const float2*)&s_t[base1];
        float2 o0, o1;
        o0.x = fmaf(bv0, s0.x, ob0 * acc[j][0]);
        o0.y = fmaf(bv0, s0.y, ob0 * acc[j][1]);
        o1.x = fmaf(bv1, s1.x, ob1 * acc[j][2]);
        o1.y = fmaf(bv1, s1.y, ob1 * acc[j][3]);
        *(float2*)&out[base0] = o0;
        *(float2*)&out[base1] = o1;
    }
}

extern "C" void kernel_launch(void* const* d_in, const int* in_sizes, int n_in,
                              void* d_out, int out_size)
{
    (void)in_sizes; (void)n_in; (void)out_size;
    const float* V   = (const float*)d_in[0];   // (B,K,H)
    const float* h_t = (const float*)d_in[1];   // (B,T,H)
    const float* s_t = (const float*)d_in[2];   // (B,T,H)
    const float* Wv  = (const float*)d_in[3];   // (K,H)
    const float* Wg  = (const float*)d_in[4];   // (K,H)
    const float* Ws_ = (const float*)d_in[5];   // (K,H)
    const float* Wh  = (const float*)d_in[6];   // (1,K)

    float* out       = (float*)d_out;
    float* out_chat  = out;                 // (B,T,H)
    float* out_alpha = out + BTH;           // (B,T,K)
    float* out_beta  = out + BTH + BTK;     // (B,T,1)

    cudaFuncSetAttribute(chat_mma_kernel,
                         cudaFuncAttributeMaxDynamicSharedMemorySize, SMEM_CHAT);

    wperm_kernel<<<192, 128>>>(Wv, Wg, Ws_);
    gemm_mma_kernel<<<708, 128>>>(V, h_t, s_t);
    zsoft_kernel<<<dim3(4, B_), 256>>>(Wh, out_alpha, out_beta);
    chat_mma_kernel<<<dim3(4, B_), 256, SMEM_CHAT>>>(V, s_t, out_alpha, out_beta, out_chat);
}

// round 11
// speedup vs baseline: 1.3299x; 1.0236x over previous
#include <cuda_runtime.h>
#include <cstdint>

// Problem dims
#define B_  256
#define T_  64
#define K_  49
#define H_  512
#define A_  49
#define BT  (B_ * T_)            // 16384
#define BK  (B_ * K_)            // 12544
#define BTH ((size_t)BT * H_)    // 8388608
#define BTK ((size_t)BT * K_)    // 802816
#define CP  52                   // padded row pitch for scratch [*, 52]

// Scratch (device globals; no allocations allowed)
__device__ __align__(16) float g_cv[B_ * K_ * CP];   // content_v  [b,k,52]
__device__ __align__(16) float g_cg[B_ * T_ * CP];   // content_g  [b,t,52]
__device__ __align__(16) float g_cs[B_ * T_ * CP];   // s_t@Ws^T   [b,t,52]
__device__ __align__(16) float g_Wp[3 * 32768];      // permuted W fragments

typedef unsigned long long u64;

__device__ __forceinline__ float tanh_approx(float x) {
    float y;
    asm("tanh.approx.f32 %0, %1;" : "=f"(y) : "f"(x));
    return y;
}
__device__ __forceinline__ u64 pack2(float lo, float hi) {
    u64 d;
    asm("mov.b64 %0, {%1, %2};" : "=l"(d) : "f"(lo), "f"(hi));
    return d;
}
__device__ __forceinline__ uint32_t s2u(const void* p) {
    uint32_t a;
    asm("{ .reg .u64 t; cvta.to.shared.u64 t, %1; cvt.u32.u64 %0, t; }"
        : "=r"(a) : "l"(p));
    return a;
}
__device__ __forceinline__ void cpa16(uint32_t dst, const void* src) {
    asm volatile("cp.async.cg.shared.global [%0], [%1], 16;"
                 :: "r"(dst), "l"(src) : "memory");
}
__device__ __forceinline__ void prefetchL2(const void* p) {
    asm volatile("prefetch.global.L2 [%0];" :: "l"(p));
}
__device__ __forceinline__ void mma_tf32(float* d,
                                         float a0, float a1, float a2, float a3,
                                         float b0, float b1) {
    asm volatile(
        "mma.sync.aligned.m16n8k8.row.col.f32.tf32.tf32.f32 "
        "{%0,%1,%2,%3}, {%4,%5,%6,%7}, {%8,%9}, {%0,%1,%2,%3};"
        : "+f"(d[0]), "+f"(d[1]), "+f"(d[2]), "+f"(d[3])
        : "r"(__float_as_uint(a0)), "r"(__float_as_uint(a1)),
          "r"(__float_as_uint(a2)), "r"(__float_as_uint(a3)),
          "r"(__float_as_uint(b0)), "r"(__float_as_uint(b1)));
}
__device__ __forceinline__ void mma_bf16(float* d,
                                         uint32_t a0, uint32_t a1, uint32_t a2, uint32_t a3,
                                         uint32_t b0, uint32_t b1) {
    asm volatile(
        "mma.sync.aligned.m16n8k16.row.col.f32.bf16.bf16.f32 "
        "{%0,%1,%2,%3}, {%4,%5,%6,%7}, {%8,%9}, {%0,%1,%2,%3};"
        : "+f"(d[0]), "+f"(d[1]), "+f"(d[2]), "+f"(d[3])
        : "r"(a0), "r"(a1), "r"(a2), "r"(a3), "r"(b0), "r"(b1));
}
__device__ __forceinline__ uint32_t bf2pack(float x0, float x1) {
    uint32_t h;
    asm("cvt.rn.bf16x2.f32 %0, %1, %2;" : "=r"(h) : "f"(x1), "f"(x0));
    return h;
}
__device__ __forceinline__ void bf2split(float x0, float x1,
                                         uint32_t& hi, uint32_t& lo) {
    hi = bf2pack(x0, x1);
    float r0 = __uint_as_float(hi << 16);
    float r1 = __uint_as_float(hi & 0xffff0000u);
    lo = bf2pack(x0 - r0, x1 - r1);
}

// ---------------------------------------------------------------------------
// Permute W matrices into mma.sync B-fragment order.
// ---------------------------------------------------------------------------
__global__ __launch_bounds__(128)
void wperm_kernel(const float* __restrict__ Wv, const float* __restrict__ Wg,
                  const float* __restrict__ Ws_)
{
    int tid = blockIdx.x * 128 + threadIdx.x;       // 0..24575
    int mat = tid / 8192;
    int rem = tid % 8192;
    int S   = rem / 128;
    int j   = (rem / 32) % 4;
    int l   = rem % 32;
    int g = l >> 2, tg = l & 3;
    int k = S * 8 + tg;
    int r0 = 16 * j + g, r1 = r0 + 8;
    const float* W = (mat == 0) ? Wv : (mat == 1) ? Wg : Ws_;
    float4 F;
    F.x = (r0 < A_) ? W[(size_t)r0 * H_ + k]     : 0.f;
    F.y = (r0 < A_) ? W[(size_t)r0 * H_ + k + 4] : 0.f;
    F.z = (r1 < A_) ? W[(size_t)r1 * H_ + k]     : 0.f;
    F.w = (r1 < A_) ? W[(size_t)r1 * H_ + k + 4] : 0.f;
    *(float4*)&g_Wp[(size_t)mat * 32768 + (size_t)rem * 4] = F;
}

// ---------------------------------------------------------------------------
// tf32 mma.sync content GEMM, double-buffered K=32 chunks, 6 CTA/SM (1 wave).
// ---------------------------------------------------------------------------
#define XPW 36     // X smem pitch (floats)

__global__ __launch_bounds__(128, 6)
void gemm_mma_kernel(const float* __restrict__ V,   const float* __restrict__ h_t,
                     const float* __restrict__ s_t)
{
    __shared__ __align__(16) float Xs[2][64][XPW];
    __shared__ __align__(16) float Bs[2][2048];

    const float* X; const float* wp; float* out; int row0;
    const int bid = blockIdx.x;
    if (bid < 196)      { X = V;   wp = g_Wp;          out = g_cv; row0 = bid * 64; }
    else if (bid < 452) { X = h_t; wp = g_Wp + 32768;  out = g_cg; row0 = (bid - 196) * 64; }
    else                { X = s_t; wp = g_Wp + 65536;  out = g_cs; row0 = (bid - 452) * 64; }

    const int tid  = threadIdx.x;
    const int wid  = tid >> 5;
    const int lane = tid & 31;
    const int g    = lane >> 2;
    const int tg   = lane & 3;
    const uint32_t xs_u[2] = { s2u(&Xs[0][0][0]), s2u(&Xs[1][0][0]) };
    const uint32_t bs_u[2] = { s2u(&Bs[0][0]),    s2u(&Bs[1][0]) };

    auto load_chunk = [&](int c) {
        const int p = c & 1;
        #pragma unroll
        for (int i = 0; i < 4; i++) {
            int idx = tid + i * 128;
            int r = idx >> 3, c4 = idx & 7;
            cpa16(xs_u[p] + (uint32_t)(r * XPW + c4 * 4) * 4,
                  &X[(size_t)(row0 + r) * H_ + c * 32 + c4 * 4]);
        }
        #pragma unroll
        for (int i = 0; i < 4; i++) {
            int idx = tid + i * 128;
            cpa16(bs_u[p] + (uint32_t)idx * 16, wp + (size_t)c * 2048 + (size_t)idx * 4);
        }
        asm volatile("cp.async.commit_group;" ::: "memory");
    };

    float acc[8][4];
    #pragma unroll
    for (int n = 0; n < 8; n++)
        #pragma unroll
        for (int c = 0; c < 4; c++) acc[n][c] = 0.f;

    load_chunk(0);
    for (int c = 0; c < 16; c++) {
        if (c + 1 < 16) {
            load_chunk(c + 1);
            asm volatile("cp.async.wait_group 1;" ::: "memory");
        } else {
            asm volatile("cp.async.wait_group 0;" ::: "memory");
        }
        __syncthreads();

        const int p = c & 1;
        #pragma unroll
        for (int s = 0; s < 4; s++) {
            float a0 = Xs[p][16*wid + g    ][s*8 + tg    ];
            float a1 = Xs[p][16*wid + g + 8][s*8 + tg    ];
            float a2 = Xs[p][16*wid + g    ][s*8 + tg + 4];
            float a3 = Xs[p][16*wid + g + 8][s*8 + tg + 4];
            #pragma unroll
            for (int j = 0; j < 4; j++) {
                float4 bf = *(const float4*)&Bs[p][((s*4 + j) * 32 + lane) * 4];
                mma_tf32(acc[2*j],     a0, a1, a2, a3, bf.x, bf.y);
                mma_tf32(acc[2*j + 1], a0, a1, a2, a3, bf.z, bf.w);
            }
        }
        __syncthreads();
    }

    const int r0g = row0 + 16 * wid + g;
    #pragma unroll
    for (int n = 0; n < 8; n++) {
        int col0 = n * 8 + tg * 2;
        if (col0 < CP) {
            *(u64*)&out[(size_t)r0g * CP + col0]       = pack2(acc[n][0], acc[n][1]);
            *(u64*)&out[(size_t)(r0g + 8) * CP + col0] = pack2(acc[n][2], acc[n][3]);
        }
    }
}

// ---------------------------------------------------------------------------
// zsoft: z_t + z_ext + softmax(alpha) + extended softmax(beta). (unchanged)
// ---------------------------------------------------------------------------
#define TZ 16
#define ZP 52

__global__ __launch_bounds__(256)
void zsoft_kernel(const float* __restrict__ Wh,
                  float* __restrict__ out_alpha, float* __restrict__ out_beta)
{
    const int b  = blockIdx.y;
    const int t0 = blockIdx.x * TZ;
    __shared__ __align__(16) float cvs[K_ * ZP];
    __shared__ __align__(16) float cgs[TZ * ZP];
    __shared__ __align__(16) float css[TZ * ZP];
    __shared__ __align__(16) float whs[52];
    __shared__ float zes[TZ];
    __shared__ float zs[TZ * 50];
    const int tid = threadIdx.x;

    for (int i = tid; i < K_ * 13; i += 256) {
        int k = i / 13, c4 = i % 13;
        *(float4*)&cvs[k * ZP + c4*4] =
            *(const float4*)&g_cv[((size_t)b * K_ + k) * CP + c4*4];
    }
    for (int i = tid; i < TZ * 13; i += 256) {
        int t = i / 13, c4 = i % 13;
        size_t src = ((size_t)b * T_ + t0 + t) * CP + c4*4;
        *(float4*)&cgs[t * ZP + c4*4] = *(const float4*)&g_cg[src];
        *(float4*)&css[t * ZP + c4*4] = *(const float4*)&g_cs[src];
    }
    if (tid < 52) whs[tid] = (tid < A_) ? Wh[tid] : 0.f;
    __syncthreads();

    for (int item = tid; item < TZ * K_ + TZ; item += 256) {
        const float* rowA;
        const float* rowB;
        if (item < TZ * K_) {
            int t = item / K_, k = item % K_;
            rowA = &cgs[t * ZP];
            rowB = &cvs[k * ZP];
        } else {
            int t = item - TZ * K_;
            rowA = &cgs[t * ZP];
            rowB = &css[t * ZP];
        }
        float s0 = 0.f, s1 = 0.f, s2 = 0.f, s3 = 0.f;
        #pragma unroll
        for (int a = 0; a < 48; a += 4) {
            float4 A = *(const float4*)&rowA[a];
            float4 Bv = *(const float4*)&rowB[a];
            float4 W = *(const float4*)&whs[a];
            s0 = fmaf(tanh_approx(A.x + Bv.x), W.x, s0);
            s1 = fmaf(tanh_approx(A.y + Bv.y), W.y, s1);
            s2 = fmaf(tanh_approx(A.z + Bv.z), W.z, s2);
            s3 = fmaf(tanh_approx(A.w + Bv.w), W.w, s3);
        }
        s0 = fmaf(tanh_approx(rowA[48] + rowB[48]), whs[48], s0);
        float z = (s0 + s1) + (s2 + s3);
        if (item < TZ * K_) {
            int t = item / K_, k = item % K_;
            zs[t * 50 + k] = z;
        } else {
            zes[item - TZ * K_] = z;
        }
    }
    __syncthreads();

    const int warp = tid >> 5, lane = tid & 31;
    for (int t = warp; t < TZ; t += 8) {
        float z1 = (lane < K_)      ? zs[t*50 + lane]      : -1e30f;
        float z2 = (lane + 32 < K_) ? zs[t*50 + lane + 32] : -1e30f;
        float m = fmaxf(z1, z2);
        #pragma unroll
        for (int o = 16; o; o >>= 1) m = fmaxf(m, __shfl_xor_sync(0xffffffffu, m, o));
        float e1 = (lane < K_)      ? __expf(z1 - m) : 0.f;
        float e2 = (lane + 32 < K_) ? __expf(z2 - m) : 0.f;
        float s = e1 + e2;
        #pragma unroll
        for (int o = 16; o; o >>= 1) s += __shfl_xor_sync(0xffffffffu, s, o);
        float inv = 1.f / s;
        size_t bt = (size_t)b * T_ + t0 + t;
        if (lane < K_)      out_alpha[bt * K_ + lane]      = e1 * inv;
        if (lane + 32 < K_) out_alpha[bt * K_ + lane + 32] = e2 * inv;
        if (lane == 0) {
            float ze = zes[t];
            float m2 = fmaxf(m, ze);
            float ee = __expf(ze - m2);
            float denom = s * __expf(m - m2) + ee;
            out_beta[bt] = ee / denom;
        }
    }
}

// ---------------------------------------------------------------------------
// chat via bf16-split m16n8k16 mma over k=0..47 (3 ksteps, 72 MMAs) with the
// k=48 term handled EXACTLY in the fp32 epilogue (v48/a48 raw rows).
// Block (hc 128-wide, b); 256 thr = 8 warps = 4 m16-tiles x 2 n64-halves.
// Smem 41.5KB -> 5 CTA/SM.
// ---------------------------------------------------------------------------
#define VPU 136            // u32 pitch of V hi/lo tiles [24 kpairs][128 n]
#define APU 28             // u32 pitch of A hi/lo tiles [64 t][24 kpairs]
#define V_U32 (24 * VPU)   // 3264
#define A_U32 (64 * APU)   // 1792
#define SMEM_CHAT ((2 * V_U32 + 2 * A_U32 + 128 + 64 + 64) * 4)   // 41472 bytes

__global__ __launch_bounds__(256, 5)
void chat_mma_kernel(const float* __restrict__ V, const float* __restrict__ s_t,
                     const float* __restrict__ alpha, const float* __restrict__ beta,
                     float* __restrict__ out)
{
    extern __shared__ __align__(16) uint32_t csm[];
    uint32_t* Vhi = csm;
    uint32_t* Vlo = csm + V_U32;
    uint32_t* Ahi = csm + 2 * V_U32;
    uint32_t* Alo = csm + 2 * V_U32 + A_U32;
    float*    v48 = (float*)(csm + 2 * V_U32 + 2 * A_U32);          // [128]
    float*    a48 = v48 + 128;                                       // [64]
    float*    bsm = a48 + 64;                                        // [64]

    const int b  = blockIdx.y;
    const int hc = blockIdx.x * 128;
    const int tid = threadIdx.x;

    // Prefetch the epilogue's s_t working set into L2.
    {
        int t = tid >> 2, ln = tid & 3;
        prefetchL2(&s_t[((size_t)b * T_ + t) * H_ + hc + ln * 32]);
    }

    // V tile: kpairs 0..23 (k 0..47), 32 f4-cols each. All real, no checks.
    for (int idx = tid; idx < 24 * 32; idx += 256) {
        int kp = idx >> 5, n4 = idx & 31;
        const float* p0 = &V[((size_t)b * K_ + 2 * kp) * H_ + hc + n4 * 4];
        float4 x0 = *(const float4*)p0;
        float4 x1 = *(const float4*)(p0 + H_);
        uint4 h, l;
        bf2split(x0.x, x1.x, h.x, l.x);
        bf2split(x0.y, x1.y, h.y, l.y);
        bf2split(x0.z, x1.z, h.z, l.z);
        bf2split(x0.w, x1.w, h.w, l.w);
        *(uint4*)&Vhi[kp * VPU + n4 * 4] = h;
        *(uint4*)&Vlo[kp * VPU + n4 * 4] = l;
    }
    // v48 row (raw fp32), a48 column, beta.
    if (tid < 32)
        *(float4*)&v48[tid * 4] =
            *(const float4*)&V[((size_t)b * K_ + 48) * H_ + hc + tid * 4];
    if (tid >= 64 && tid < 128) {
        int t = tid - 64;
        a48[t] = alpha[((size_t)b * T_ + t) * K_ + 48];
    }
    if (tid >= 128 && tid < 192) {
        int t = tid - 128;
        bsm[t] = beta[(size_t)b * T_ + t];
    }
    // Alpha: 64 t x 24 kpairs (k 0..47, all real).
    for (int idx = tid; idx < 64 * 24; idx += 256) {
        int t = idx / 24, kp = idx % 24;
        const float* ap = &alpha[((size_t)b * T_ + t) * K_ + 2 * kp];
        uint32_t h, l;
        bf2split(ap[0], ap[1], h, l);
        Ahi[t * APU + kp] = h;
        Alo[t * APU + kp] = l;
    }
    __syncthreads();

    const int wid  = tid >> 5;
    const int lane = tid & 31;
    const int g    = lane >> 2;
    const int tg   = lane & 3;
    const int mw   = wid & 3;      // m16 tile (t-range 16mw..16mw+15)
    const int nh   = wid >> 2;     // n 64-half
    const int row  = 16 * mw + g;

    float acc[8][4];
    #pragma unroll
    for (int j = 0; j < 8; j++)
        #pragma unroll
        for (int c = 0; c < 4; c++) acc[j][c] = 0.f;

    #pragma unroll
    for (int ks = 0; ks < 3; ks++) {
        uint32_t ah0 = Ahi[ row      * APU + ks*8 + tg    ];
        uint32_t ah1 = Ahi[(row + 8) * APU + ks*8 + tg    ];
        uint32_t ah2 = Ahi[ row      * APU + ks*8 + tg + 4];
        uint32_t ah3 = Ahi[(row + 8) * APU + ks*8 + tg + 4];
        uint32_t al0 = Alo[ row      * APU + ks*8 + tg    ];
        uint32_t al1 = Alo[(row + 8) * APU + ks*8 + tg    ];
        uint32_t al2 = Alo[ row      * APU + ks*8 + tg + 4];
        uint32_t al3 = Alo[(row + 8) * APU + ks*8 + tg + 4];
        #pragma unroll
        for (int j = 0; j < 8; j++) {
            int n = nh*64 + j*8 + g;
            uint32_t bh0 = Vhi[(ks*8 + tg    ) * VPU + n];
            uint32_t bh1 = Vhi[(ks*8 + tg + 4) * VPU + n];
            uint32_t bl0 = Vlo[(ks*8 + tg    ) * VPU + n];
            uint32_t bl1 = Vlo[(ks*8 + tg + 4) * VPU + n];
            mma_bf16(acc[j], ah0, ah1, ah2, ah3, bh0, bh1);   // hi*hi
            mma_bf16(acc[j], ah0, ah1, ah2, ah3, bl0, bl1);   // hi*lo
            mma_bf16(acc[j], al0, al1, al2, al3, bh0, bh1);   // lo*hi
        }
    }

    // Epilogue: add exact k=48 term, then beta-blend.
    const float a48r0 = a48[row], a48r1 = a48[row + 8];
    const float bv0 = bsm[row],     ob0 = 1.f - bv0;
    const float bv1 = bsm[row + 8], ob1 = 1.f - bv1;
    #pragma unroll
    for (int j = 0; j < 8; j++) {
        int n0 = nh*64 + j*8 + 2*tg;
        float v0 = v48[n0], v1 = v48[n0 + 1];
        float c00 = fmaf(a48r0, v0, acc[j][0]);
        float c01 = fmaf(a48r0, v1, acc[j][1]);
        float c10 = fmaf(a48r1, v0, acc[j][2]);
        float c11 = fmaf(a48r1, v1, acc[j][3]);
        int col = hc + n0;
        size_t base0 = ((size_t)b * T_ + row)     * H_ + col;
        size_t base1 = ((size_t)b * T_ + row + 8) * H_ + col;
        float2 s0 = *(const float2*)&s_t[base0];
        float2 s1 = *(const float2*)&s_t[base1];
        float2 o0, o1;
        o0.x = fmaf(bv0, s0.x, ob0 * c00);
        o0.y = fmaf(bv0, s0.y, ob0 * c01);
        o1.x = fmaf(bv1, s1.x, ob1 * c10);
        o1.y = fmaf(bv1, s1.y, ob1 * c11);
        *(float2*)&out[base0] = o0;
        *(float2*)&out[base1] = o1;
    }
}

extern "C" void kernel_launch(void* const* d_in, const int* in_sizes, int n_in,
                              void* d_out, int out_size)
{
    (void)in_sizes; (void)n_in; (void)out_size;
    const float* V   = (const float*)d_in[0];   // (B,K,H)
    const float* h_t = (const float*)d_in[1];   // (B,T,H)
    const float* s_t = (const float*)d_in[2];   // (B,T,H)
    const float* Wv  = (const float*)d_in[3];   // (K,H)
    const float* Wg  = (const float*)d_in[4];   // (K,H)
    const float* Ws_ = (const float*)d_in[5];   // (K,H)
    const float* Wh  = (const float*)d_in[6];   // (1,K)

    float* out       = (float*)d_out;
    float* out_chat  = out;                 // (B,T,H)
    float* out_alpha = out + BTH;           // (B,T,K)
    float* out_beta  = out + BTH + BTK;     // (B,T,1)

    cudaFuncSetAttribute(chat_mma_kernel,
                         cudaFuncAttributeMaxDynamicSharedMemorySize, SMEM_CHAT);

    wperm_kernel<<<192, 128>>>(Wv, Wg, Ws_);
    gemm_mma_kernel<<<708, 128>>>(V, h_t, s_t);
    zsoft_kernel<<<dim3(4, B_), 256>>>(Wh, out_alpha, out_beta);
    chat_mma_kernel<<<dim3(4, B_), 256, SMEM_CHAT>>>(V, s_t, out_alpha, out_beta, out_chat);
}

// round 12
// speedup vs baseline: 1.3776x; 1.0359x over previous
#include <cuda_runtime.h>
#include <cstdint>

// Problem dims
#define B_  256
#define T_  64
#define K_  49
#define H_  512
#define A_  49
#define BT  (B_ * T_)            // 16384
#define BK  (B_ * K_)            // 12544
#define BTH ((size_t)BT * H_)    // 8388608
#define BTK ((size_t)BT * K_)    // 802816
#define CP  52                   // padded row pitch for scratch [*, 52]

// Scratch (device globals; no allocations allowed)
__device__ __align__(16) float    g_cv[B_ * K_ * CP];   // content_v  [b,k,52]
__device__ __align__(16) float    g_cg[B_ * T_ * CP];   // content_g  [b,t,52]
__device__ __align__(16) float    g_cs[B_ * T_ * CP];   // s_t@Ws^T   [b,t,52]
__device__ __align__(16) float    g_Wp[3 * 32768];      // permuted W fragments
__device__ __align__(16) uint32_t g_ahi[BT * 32];       // alpha hi bf16x2 [bt][kpair]
__device__ __align__(16) uint32_t g_alo[BT * 32];       // alpha lo bf16x2 [bt][kpair]

typedef unsigned long long u64;

__device__ __forceinline__ float tanh_approx(float x) {
    float y;
    asm("tanh.approx.f32 %0, %1;" : "=f"(y) : "f"(x));
    return y;
}
__device__ __forceinline__ u64 pack2(float lo, float hi) {
    u64 d;
    asm("mov.b64 %0, {%1, %2};" : "=l"(d) : "f"(lo), "f"(hi));
    return d;
}
__device__ __forceinline__ uint32_t s2u(const void* p) {
    uint32_t a;
    asm("{ .reg .u64 t; cvta.to.shared.u64 t, %1; cvt.u32.u64 %0, t; }"
        : "=r"(a) : "l"(p));
    return a;
}
__device__ __forceinline__ void cpa16(uint32_t dst, const void* src) {
    asm volatile("cp.async.cg.shared.global [%0], [%1], 16;"
                 :: "r"(dst), "l"(src) : "memory");
}
__device__ __forceinline__ void prefetchL2(const void* p) {
    asm volatile("prefetch.global.L2 [%0];" :: "l"(p));
}
__device__ __forceinline__ void mma_tf32(float* d,
                                         float a0, float a1, float a2, float a3,
                                         float b0, float b1) {
    asm volatile(
        "mma.sync.aligned.m16n8k8.row.col.f32.tf32.tf32.f32 "
        "{%0,%1,%2,%3}, {%4,%5,%6,%7}, {%8,%9}, {%0,%1,%2,%3};"
        : "+f"(d[0]), "+f"(d[1]), "+f"(d[2]), "+f"(d[3])
        : "r"(__float_as_uint(a0)), "r"(__float_as_uint(a1)),
          "r"(__float_as_uint(a2)), "r"(__float_as_uint(a3)),
          "r"(__float_as_uint(b0)), "r"(__float_as_uint(b1)));
}
__device__ __forceinline__ void mma_bf16(float* d,
                                         uint32_t a0, uint32_t a1, uint32_t a2, uint32_t a3,
                                         uint32_t b0, uint32_t b1) {
    asm volatile(
        "mma.sync.aligned.m16n8k16.row.col.f32.bf16.bf16.f32 "
        "{%0,%1,%2,%3}, {%4,%5,%6,%7}, {%8,%9}, {%0,%1,%2,%3};"
        : "+f"(d[0]), "+f"(d[1]), "+f"(d[2]), "+f"(d[3])
        : "r"(a0), "r"(a1), "r"(a2), "r"(a3), "r"(b0), "r"(b1));
}
__device__ __forceinline__ uint32_t bf2pack(float x0, float x1) {
    uint32_t h;
    asm("cvt.rn.bf16x2.f32 %0, %1, %2;" : "=r"(h) : "f"(x1), "f"(x0));
    return h;
}
__device__ __forceinline__ void bf2split(float x0, float x1,
                                         uint32_t& hi, uint32_t& lo) {
    hi = bf2pack(x0, x1);
    float r0 = __uint_as_float(hi << 16);
    float r1 = __uint_as_float(hi & 0xffff0000u);
    lo = bf2pack(x0 - r0, x1 - r1);
}

// ---------------------------------------------------------------------------
// Permute W matrices into mma.sync B-fragment order.
// ---------------------------------------------------------------------------
__global__ __launch_bounds__(128)
void wperm_kernel(const float* __restrict__ Wv, const float* __restrict__ Wg,
                  const float* __restrict__ Ws_)
{
    int tid = blockIdx.x * 128 + threadIdx.x;       // 0..24575
    int mat = tid / 8192;
    int rem = tid % 8192;
    int S   = rem / 128;
    int j   = (rem / 32) % 4;
    int l   = rem % 32;
    int g = l >> 2, tg = l & 3;
    int k = S * 8 + tg;
    int r0 = 16 * j + g, r1 = r0 + 8;
    const float* W = (mat == 0) ? Wv : (mat == 1) ? Wg : Ws_;
    float4 F;
    F.x = (r0 < A_) ? W[(size_t)r0 * H_ + k]     : 0.f;
    F.y = (r0 < A_) ? W[(size_t)r0 * H_ + k + 4] : 0.f;
    F.z = (r1 < A_) ? W[(size_t)r1 * H_ + k]     : 0.f;
    F.w = (r1 < A_) ? W[(size_t)r1 * H_ + k + 4] : 0.f;
    *(float4*)&g_Wp[(size_t)mat * 32768 + (size_t)rem * 4] = F;
}

// ---------------------------------------------------------------------------
// tf32 mma.sync content GEMM, double-buffered K=32 chunks, 6 CTA/SM (1 wave).
// ---------------------------------------------------------------------------
#define XPW 36     // X smem pitch (floats)

__global__ __launch_bounds__(128, 6)
void gemm_mma_kernel(const float* __restrict__ V,   const float* __restrict__ h_t,
                     const float* __restrict__ s_t)
{
    __shared__ __align__(16) float Xs[2][64][XPW];
    __shared__ __align__(16) float Bs[2][2048];

    const float* X; const float* wp; float* out; int row0;
    const int bid = blockIdx.x;
    if (bid < 196)      { X = V;   wp = g_Wp;          out = g_cv; row0 = bid * 64; }
    else if (bid < 452) { X = h_t; wp = g_Wp + 32768;  out = g_cg; row0 = (bid - 196) * 64; }
    else                { X = s_t; wp = g_Wp + 65536;  out = g_cs; row0 = (bid - 452) * 64; }

    const int tid  = threadIdx.x;
    const int wid  = tid >> 5;
    const int lane = tid & 31;
    const int g    = lane >> 2;
    const int tg   = lane & 3;
    const uint32_t xs_u[2] = { s2u(&Xs[0][0][0]), s2u(&Xs[1][0][0]) };
    const uint32_t bs_u[2] = { s2u(&Bs[0][0]),    s2u(&Bs[1][0]) };

    auto load_chunk = [&](int c) {
        const int p = c & 1;
        #pragma unroll
        for (int i = 0; i < 4; i++) {
            int idx = tid + i * 128;
            int r = idx >> 3, c4 = idx & 7;
            cpa16(xs_u[p] + (uint32_t)(r * XPW + c4 * 4) * 4,
                  &X[(size_t)(row0 + r) * H_ + c * 32 + c4 * 4]);
        }
        #pragma unroll
        for (int i = 0; i < 4; i++) {
            int idx = tid + i * 128;
            cpa16(bs_u[p] + (uint32_t)idx * 16, wp + (size_t)c * 2048 + (size_t)idx * 4);
        }
        asm volatile("cp.async.commit_group;" ::: "memory");
    };

    float acc[8][4];
    #pragma unroll
    for (int n = 0; n < 8; n++)
        #pragma unroll
        for (int c = 0; c < 4; c++) acc[n][c] = 0.f;

    load_chunk(0);
    for (int c = 0; c < 16; c++) {
        if (c + 1 < 16) {
            load_chunk(c + 1);
            asm volatile("cp.async.wait_group 1;" ::: "memory");
        } else {
            asm volatile("cp.async.wait_group 0;" ::: "memory");
        }
        __syncthreads();

        const int p = c & 1;
        #pragma unroll
        for (int s = 0; s < 4; s++) {
            float a0 = Xs[p][16*wid + g    ][s*8 + tg    ];
            float a1 = Xs[p][16*wid + g + 8][s*8 + tg    ];
            float a2 = Xs[p][16*wid + g    ][s*8 + tg + 4];
            float a3 = Xs[p][16*wid + g + 8][s*8 + tg + 4];
            #pragma unroll
            for (int j = 0; j < 4; j++) {
                float4 bf = *(const float4*)&Bs[p][((s*4 + j) * 32 + lane) * 4];
                mma_tf32(acc[2*j],     a0, a1, a2, a3, bf.x, bf.y);
                mma_tf32(acc[2*j + 1], a0, a1, a2, a3, bf.z, bf.w);
            }
        }
        __syncthreads();
    }

    const int r0g = row0 + 16 * wid + g;
    #pragma unroll
    for (int n = 0; n < 8; n++) {
        int col0 = n * 8 + tg * 2;
        if (col0 < CP) {
            *(u64*)&out[(size_t)r0g * CP + col0]       = pack2(acc[n][0], acc[n][1]);
            *(u64*)&out[(size_t)(r0g + 8) * CP + col0] = pack2(acc[n][2], acc[n][3]);
        }
    }
}

// ---------------------------------------------------------------------------
// zsoft: z_t + z_ext + softmax(alpha) + extended softmax(beta).
// Also emits pre-split bf16 hi/lo alpha tiles (g_ahi/g_alo) for chat.
// ---------------------------------------------------------------------------
#define TZ 16
#define ZP 52

__global__ __launch_bounds__(256)
void zsoft_kernel(const float* __restrict__ Wh,
                  float* __restrict__ out_alpha, float* __restrict__ out_beta)
{
    const int b  = blockIdx.y;
    const int t0 = blockIdx.x * TZ;
    __shared__ __align__(16) float cvs[K_ * ZP];
    __shared__ __align__(16) float cgs[TZ * ZP];
    __shared__ __align__(16) float css[TZ * ZP];
    __shared__ __align__(16) float whs[52];
    __shared__ float zes[TZ];
    __shared__ float zs[TZ * 50];
    const int tid = threadIdx.x;

    for (int i = tid; i < K_ * 13; i += 256) {
        int k = i / 13, c4 = i % 13;
        *(float4*)&cvs[k * ZP + c4*4] =
            *(const float4*)&g_cv[((size_t)b * K_ + k) * CP + c4*4];
    }
    for (int i = tid; i < TZ * 13; i += 256) {
        int t = i / 13, c4 = i % 13;
        size_t src = ((size_t)b * T_ + t0 + t) * CP + c4*4;
        *(float4*)&cgs[t * ZP + c4*4] = *(const float4*)&g_cg[src];
        *(float4*)&css[t * ZP + c4*4] = *(const float4*)&g_cs[src];
    }
    if (tid < 52) whs[tid] = (tid < A_) ? Wh[tid] : 0.f;
    __syncthreads();

    for (int item = tid; item < TZ * K_ + TZ; item += 256) {
        const float* rowA;
        const float* rowB;
        if (item < TZ * K_) {
            int t = item / K_, k = item % K_;
            rowA = &cgs[t * ZP];
            rowB = &cvs[k * ZP];
        } else {
            int t = item - TZ * K_;
            rowA = &cgs[t * ZP];
            rowB = &css[t * ZP];
        }
        float s0 = 0.f, s1 = 0.f, s2 = 0.f, s3 = 0.f;
        #pragma unroll
        for (int a = 0; a < 48; a += 4) {
            float4 A = *(const float4*)&rowA[a];
            float4 Bv = *(const float4*)&rowB[a];
            float4 W = *(const float4*)&whs[a];
            s0 = fmaf(tanh_approx(A.x + Bv.x), W.x, s0);
            s1 = fmaf(tanh_approx(A.y + Bv.y), W.y, s1);
            s2 = fmaf(tanh_approx(A.z + Bv.z), W.z, s2);
            s3 = fmaf(tanh_approx(A.w + Bv.w), W.w, s3);
        }
        s0 = fmaf(tanh_approx(rowA[48] + rowB[48]), whs[48], s0);
        float z = (s0 + s1) + (s2 + s3);
        if (item < TZ * K_) {
            int t = item / K_, k = item % K_;
            zs[t * 50 + k] = z;
        } else {
            zes[item - TZ * K_] = z;
        }
    }
    __syncthreads();

    const int warp = tid >> 5, lane = tid & 31;
    for (int t = warp; t < TZ; t += 8) {
        float z1 = (lane < K_)      ? zs[t*50 + lane]      : -1e30f;
        float z2 = (lane + 32 < K_) ? zs[t*50 + lane + 32] : -1e30f;
        float m = fmaxf(z1, z2);
        #pragma unroll
        for (int o = 16; o; o >>= 1) m = fmaxf(m, __shfl_xor_sync(0xffffffffu, m, o));
        float e1 = (lane < K_)      ? __expf(z1 - m) : 0.f;
        float e2 = (lane + 32 < K_) ? __expf(z2 - m) : 0.f;
        float s = e1 + e2;
        #pragma unroll
        for (int o = 16; o; o >>= 1) s += __shfl_xor_sync(0xffffffffu, s, o);
        float inv = 1.f / s;
        size_t bt = (size_t)b * T_ + t0 + t;
        float a1v = e1 * inv, a2v = e2 * inv;
        if (lane < K_) {
            out_alpha[bt * K_ + lane] = a1v;
            zs[t*50 + lane] = a1v;                 // overwrite z with alpha
        }
        if (lane + 32 < K_) {
            out_alpha[bt * K_ + lane + 32] = a2v;
            zs[t*50 + lane + 32] = a2v;
        }
        if (lane == 0) {
            float ze = zes[t];
            float m2 = fmaxf(m, ze);
            float ee = __expf(ze - m2);
            float denom = s * __expf(m - m2) + ee;
            out_beta[bt] = ee / denom;
        }
    }
    __syncthreads();

    // Emit pre-split bf16 alpha tiles: [bt][32 kpairs], kpairs >= 25 zero.
    for (int item = tid; item < TZ * 32; item += 256) {
        int t = item >> 5, kp = item & 31;
        float x0 = (2*kp     < K_) ? zs[t*50 + 2*kp]     : 0.f;
        float x1 = (2*kp + 1 < K_) ? zs[t*50 + 2*kp + 1] : 0.f;
        uint32_t h, l;
        bf2split(x0, x1, h, l);
        size_t dst = ((size_t)b * T_ + t0 + t) * 32 + kp;
        g_ahi[dst] = h;
        g_alo[dst] = l;
    }
}

// ---------------------------------------------------------------------------
// chat via 2-term bf16-split m16n8k16 mma (round-10 structure), with alpha
// hi/lo tiles loaded pre-split from zsoft via cp.async (no scalar loads, no
// split chains in this kernel's prologue for alpha).
// ---------------------------------------------------------------------------
#define VPU 136            // u32 pitch of V hi/lo tiles [32 kpairs][128 n]
#define APU 36             // u32 pitch of A hi/lo tiles [64 t][32 kpairs]
#define V_U32 (32 * VPU)   // 4352
#define A_U32 (64 * APU)   // 2304
#define SMEM_CHAT ((2 * V_U32 + 2 * A_U32 + 64) * 4)   // 53504 bytes

__global__ __launch_bounds__(256)
void chat_mma_kernel(const float* __restrict__ V, const float* __restrict__ s_t,
                     const float* __restrict__ beta, float* __restrict__ out)
{
    extern __shared__ __align__(16) uint32_t csm[];
    uint32_t* Vhi = csm;
    uint32_t* Vlo = csm + V_U32;
    uint32_t* Ahi = csm + 2 * V_U32;
    uint32_t* Alo = csm + 2 * V_U32 + A_U32;
    float*    bsm = (float*)(csm + 2 * V_U32 + 2 * A_U32);

    const int b  = blockIdx.y;
    const int hc = blockIdx.x * 128;
    const int tid = threadIdx.x;
    const uint32_t ahi_u = s2u(Ahi);
    const uint32_t alo_u = s2u(Alo);

    // Prefetch the epilogue's s_t working set into L2.
    {
        int t = tid >> 2, ln = tid & 3;
        prefetchL2(&s_t[((size_t)b * T_ + t) * H_ + hc + ln * 32]);
    }

    // Alpha hi/lo tiles via cp.async: 64 rows x 8 16B-chunks each.
    #pragma unroll
    for (int i = 0; i < 2; i++) {
        int idx = tid + i * 256;
        int row = idx >> 3, c4 = idx & 7;
        cpa16(ahi_u + (uint32_t)(row * APU + c4 * 4) * 4,
              &g_ahi[((size_t)b * T_ + row) * 32 + c4 * 4]);
        cpa16(alo_u + (uint32_t)(row * APU + c4 * 4) * 4,
              &g_alo[((size_t)b * T_ + row) * 32 + c4 * 4]);
    }
    asm volatile("cp.async.commit_group;" ::: "memory");

    // V tile: 25 kpairs x 32 float4-cols (k >= 49 zero), split to hi/lo.
    for (int idx = tid; idx < 25 * 32; idx += 256) {
        int kp = idx >> 5, n4 = idx & 31;
        const float* p0 = &V[((size_t)b * K_ + 2 * kp) * H_ + hc + n4 * 4];
        float4 x0 = *(const float4*)p0;
        float4 x1 = make_float4(0.f, 0.f, 0.f, 0.f);
        if (2 * kp + 1 < K_) x1 = *(const float4*)(p0 + H_);
        uint4 h, l;
        bf2split(x0.x, x1.x, h.x, l.x);
        bf2split(x0.y, x1.y, h.y, l.y);
        bf2split(x0.z, x1.z, h.z, l.z);
        bf2split(x0.w, x1.w, h.w, l.w);
        *(uint4*)&Vhi[kp * VPU + n4 * 4] = h;
        *(uint4*)&Vlo[kp * VPU + n4 * 4] = l;
    }
    for (int idx = tid; idx < 2 * 7 * 32; idx += 256) {
        int p = idx / 224, r = idx % 224;
        int kp = 25 + r / 32, n4 = r % 32;
        uint32_t* dst = p ? Vlo : Vhi;
        *(uint4*)&dst[kp * VPU + n4 * 4] = make_uint4(0, 0, 0, 0);
    }
    if (tid < T_) bsm[tid] = beta[(size_t)b * T_ + tid];
    asm volatile("cp.async.wait_group 0;" ::: "memory");
    __syncthreads();

    const int wid  = tid >> 5;
    const int lane = tid & 31;
    const int g    = lane >> 2;
    const int tg   = lane & 3;
    const int mw   = wid & 3;
    const int nh   = wid >> 2;
    const int row  = 16 * mw + g;

    float acc[8][4];
    #pragma unroll
    for (int j = 0; j < 8; j++)
        #pragma unroll
        for (int c = 0; c < 4; c++) acc[j][c] = 0.f;

    #pragma unroll
    for (int ks = 0; ks < 4; ks++) {
        uint32_t ah0 = Ahi[ row      * APU + ks*8 + tg    ];
        uint32_t ah1 = Ahi[(row + 8) * APU + ks*8 + tg    ];
        uint32_t ah2 = Ahi[ row      * APU + ks*8 + tg + 4];
        uint32_t ah3 = Ahi[(row + 8) * APU + ks*8 + tg + 4];
        uint32_t al0 = Alo[ row      * APU + ks*8 + tg    ];
        uint32_t al1 = Alo[(row + 8) * APU + ks*8 + tg    ];
        uint32_t al2 = Alo[ row      * APU + ks*8 + tg + 4];
        uint32_t al3 = Alo[(row + 8) * APU + ks*8 + tg + 4];
        #pragma unroll
        for (int j = 0; j < 8; j++) {
            int n = nh*64 + j*8 + g;
            uint32_t bh0 = Vhi[(ks*8 + tg    ) * VPU + n];
            uint32_t bh1 = Vhi[(ks*8 + tg + 4) * VPU + n];
            uint32_t bl0 = Vlo[(ks*8 + tg    ) * VPU + n];
            uint32_t bl1 = Vlo[(ks*8 + tg + 4) * VPU + n];
            mma_bf16(acc[j], ah0, ah1, ah2, ah3, bh0, bh1);   // hi*hi
            mma_bf16(acc[j], ah0, ah1, ah2, ah3, bl0, bl1);   // hi*lo
            mma_bf16(acc[j], al0, al1, al2, al3, bh0, bh1);   // lo*hi
        }
    }

    const float bv0 = bsm[row],     ob0 = 1.f - bv0;
    const float bv1 = bsm[row + 8], ob1 = 1.f - bv1;
    #pragma unroll
    for (int j = 0; j < 8; j++) {
        int col = hc + nh*64 + j*8 + 2*tg;
        size_t base0 = ((size_t)b * T_ + row)     * H_ + col;
        size_t base1 = ((size_t)b * T_ + row + 8) * H_ + col;
        float2 s0 = *(const float2*)&s_t[base0];
        float2 s1 = *(const float2*)&s_t[base1];
        float2 o0, o1;
        o0.x = fmaf(bv0, s0.x, ob0 * acc[j][0]);
        o0.y = fmaf(bv0, s0.y, ob0 * acc[j][1]);
        o1.x = fmaf(bv1, s1.x, ob1 * acc[j][2]);
        o1.y = fmaf(bv1, s1.y, ob1 * acc[j][3]);
        *(float2*)&out[base0] = o0;
        *(float2*)&out[base1] = o1;
    }
}

extern "C" void kernel_launch(void* const* d_in, const int* in_sizes, int n_in,
                              void* d_out, int out_size)
{
    (void)in_sizes; (void)n_in; (void)out_size;
    const float* V   = (const float*)d_in[0];   // (B,K,H)
    const float* h_t = (const float*)d_in[1];   // (B,T,H)
    const float* s_t = (const float*)d_in[2];   // (B,T,H)
    const float* Wv  = (const float*)d_in[3];   // (K,H)
    const float* Wg  = (const float*)d_in[4];   // (K,H)
    const float* Ws_ = (const float*)d_in[5];   // (K,H)
    const float* Wh  = (const float*)d_in[6];   // (1,K)

    float* out       = (float*)d_out;
    float* out_chat  = out;                 // (B,T,H)
    float* out_alpha = out + BTH;           // (B,T,K)
    float* out_beta  = out + BTH + BTK;     // (B,T,1)

    cudaFuncSetAttribute(chat_mma_kernel,
                         cudaFuncAttributeMaxDynamicSharedMemorySize, SMEM_CHAT);

    wperm_kernel<<<192, 128>>>(Wv, Wg, Ws_);
    gemm_mma_kernel<<<708, 128>>>(V, h_t, s_t);
    zsoft_kernel<<<dim3(4, B_), 256>>>(Wh, out_alpha, out_beta);
    chat_mma_kernel<<<dim3(4, B_), 256, SMEM_CHAT>>>(V, s_t, out_beta, out_chat);
}